// round 11
// baseline (speedup 1.0000x reference)
#include <cuda_runtime.h>
#include <cuda_bf16.h>
#include <cstdint>

#define NN 50000
#define EE 800000
#define FF 128
#define HH 256
#define CC 40
#define PSTR 64                   // padded p row stride

// ---------------- scratch (device globals; no runtime allocation) ----------
__device__ __nv_bfloat16 g_a16[(size_t)NN * 2 * FF];   // split agg(x)  [N,256]=[hi|lo]
__device__ __nv_bfloat16 g_w16[(size_t)HH * 2 * FF];   // split W1 [256][hi128|lo128]
__device__ __nv_bfloat16 g_wf16[(size_t)64 * 2 * HH];  // split Wf [64][hi256|lo256]
__device__ float g_p[(size_t)NN * PSTR];               // pre-agg logits [N,40] pad 64
__device__ float g_biasf[CC];                          // fused bias
__device__ int   g_deg[NN];
__device__ float g_dinv[NN];
__device__ int   g_rowptr[NN];
__device__ int   g_cursor[NN];
__device__ int   g_csrc[EE];
__device__ float g_cw[EE];                             // per-edge dinv[src]

// ---------------- combined prep ---------------------------------------------
// blocks 0..127   : split W1 (256x128) -> g_w16 rows [hi128|lo128]
// blocks 128..167 : c = b-128: Wf row c = Wout[c]@W2 (fp32), split -> g_wf16;
//                   biasf[c] = bout[c] + Wout[c]@b2
// block 168       : zero-pad g_wf16 rows 40..63
// blocks 169..364 : zero g_deg
__global__ void prep_kernel(const float* __restrict__ W1, const float* __restrict__ W2,
                            const float* __restrict__ Wout, const float* __restrict__ b2,
                            const float* __restrict__ bout) {
    __shared__ float sh[256];
    int b = blockIdx.x;
    int t = threadIdx.x;
    if (b < 128) {
        int idx = b * 256 + t;
        int n = idx >> 7;            // row 0..255
        int k = idx & 127;
        float v = W1[(size_t)n * FF + k];
        __nv_bfloat16 hi = __float2bfloat16(v);
        __nv_bfloat16 lo = __float2bfloat16(v - __bfloat162float(hi));
        g_w16[(size_t)n * (2 * FF) + k]      = hi;
        g_w16[(size_t)n * (2 * FF) + FF + k] = lo;
    } else if (b < 168) {
        int c = b - 128;             // 0..39
        float wc = Wout[(size_t)c * HH + t];
        float acc = 0.0f;
        #pragma unroll 4
        for (int o = 0; o < HH; o++)
            acc += Wout[(size_t)c * HH + o] * W2[(size_t)o * HH + t];
        __nv_bfloat16 hi = __float2bfloat16(acc);
        __nv_bfloat16 lo = __float2bfloat16(acc - __bfloat162float(hi));
        g_wf16[(size_t)c * (2 * HH) + t]      = hi;
        g_wf16[(size_t)c * (2 * HH) + HH + t] = lo;
        sh[t] = wc * b2[t];
        __syncthreads();
        for (int off = 128; off > 0; off >>= 1) {
            if (t < off) sh[t] += sh[t + off];
            __syncthreads();
        }
        if (t == 0) g_biasf[c] = bout[c] + sh[0];
    } else if (b == 168) {
        __nv_bfloat16 z = __float2bfloat16(0.0f);
        for (int idx = t; idx < 24 * 2 * HH; idx += 256)
            g_wf16[(size_t)40 * (2 * HH) + idx] = z;
    } else {
        int i = (b - 169) * 256 + t;
        if (i < NN) g_deg[i] = 0;
    }
}

// ---------------- CSR build ------------------------------------------------
__global__ void count_deg_kernel(const int* __restrict__ dst) {
    int e = blockIdx.x * blockDim.x + threadIdx.x;
    if (e < EE) atomicAdd(&g_deg[dst[e]], 1);
}

// single-pass exclusive scan over g_deg: one block, 1024 threads, 49 chunks.
// Also writes g_cursor (= rowptr) and g_dinv.
__global__ __launch_bounds__(1024)
void scan_kernel() {
    __shared__ int sm[32];
    int t = threadIdx.x;
    int lane = t & 31;
    int w = t >> 5;
    int running = 0;

    for (int chunk = 0; chunk < NN; chunk += 1024) {
        int i = chunk + t;
        int v = (i < NN) ? g_deg[i] : 0;

        // warp inclusive scan
        int incl = v;
        #pragma unroll
        for (int o = 1; o < 32; o <<= 1) {
            int n = __shfl_up_sync(~0u, incl, o);
            if (lane >= o) incl += n;
        }
        if (lane == 31) sm[w] = incl;
        __syncthreads();
        if (w == 0) {
            int s = sm[lane];
            #pragma unroll
            for (int o = 1; o < 32; o <<= 1) {
                int n = __shfl_up_sync(~0u, s, o);
                if (lane >= o) s += n;
            }
            sm[lane] = s;
        }
        __syncthreads();
        int woff = w ? sm[w - 1] : 0;
        int total = sm[31];
        int excl = running + woff + incl - v;

        if (i < NN) {
            g_rowptr[i] = excl;
            g_cursor[i] = excl;
            g_dinv[i] = rsqrtf((float)v + 1.0f);
        }
        running += total;
        __syncthreads();   // protect sm before next chunk
    }
}

__global__ void fill_csr_kernel(const int* __restrict__ src, const int* __restrict__ dst) {
    int e = blockIdx.x * blockDim.x + threadIdx.x;
    if (e < EE) {
        int s = src[e];
        int pos = atomicAdd(&g_cursor[dst[e]], 1);
        g_csrc[pos] = s;
        g_cw[pos] = g_dinv[s];
    }
}

// ---------------- agg(x) with split-bf16 output -----------------------------
__global__ __launch_bounds__(FF)
void aggregate_split_kernel(const float* __restrict__ h) {
    int i = blockIdx.x;
    int c = threadIdx.x;
    __shared__ int   s_src[FF];
    __shared__ float s_w[FF];

    int start = g_rowptr[i];
    int d = g_deg[i];
    float di = g_dinv[i];
    float acc = 0.0f;

    if (d <= FF) {
        if (c < d) {
            s_src[c] = g_csrc[start + c];
            s_w[c] = g_cw[start + c];
        }
        __syncthreads();
        #pragma unroll 8
        for (int j = 0; j < d; j++)
            acc += s_w[j] * h[(size_t)s_src[j] * FF + c];
    } else {
        for (int base = 0; base < d; base += FF) {
            int n = d - base;
            if (n > FF) n = FF;
            __syncthreads();
            if (c < n) {
                s_src[c] = g_csrc[start + base + c];
                s_w[c] = g_cw[start + base + c];
            }
            __syncthreads();
            #pragma unroll 8
            for (int j = 0; j < n; j++)
                acc += s_w[j] * h[(size_t)s_src[j] * FF + c];
        }
    }

    float v = di * acc + di * di * h[(size_t)i * FF + c];
    __nv_bfloat16 hi = __float2bfloat16(v);
    __nv_bfloat16 lo = __float2bfloat16(v - __bfloat162float(hi));
    size_t b = (size_t)i * (2 * FF);
    g_a16[b + c]      = hi;
    g_a16[b + FF + c] = lo;
}

// ---------------- mma helpers -----------------------------------------------
__device__ __forceinline__ void ldmx4(uint32_t* r, const __nv_bfloat16* p) {
    uint32_t addr = (uint32_t)__cvta_generic_to_shared(p);
    asm volatile("ldmatrix.sync.aligned.m8n8.x4.shared.b16 {%0,%1,%2,%3}, [%4];"
                 : "=r"(r[0]), "=r"(r[1]), "=r"(r[2]), "=r"(r[3]) : "r"(addr));
}

__device__ __forceinline__ void mma16816(float* d, const uint32_t* a, const uint32_t* b) {
    asm volatile(
        "mma.sync.aligned.m16n8k16.row.col.f32.bf16.bf16.f32 "
        "{%0,%1,%2,%3}, {%4,%5,%6,%7}, {%8,%9}, {%0,%1,%2,%3};"
        : "+f"(d[0]), "+f"(d[1]), "+f"(d[2]), "+f"(d[3])
        : "r"(a[0]), "r"(a[1]), "r"(a[2]), "r"(a[3]), "r"(b[0]), "r"(b[1]));
}

// ---------------- B2B kernel: p = relu(a16*W1'^T+b1) * Wf'^T ----------------
#define HSTR 136
#define ATP 40

__global__ __launch_bounds__(256, 2)
void b2b_kernel(const __nv_bfloat16* __restrict__ A,
                const __nv_bfloat16* __restrict__ W1s,
                const __nv_bfloat16* __restrict__ Wf16,
                const float* __restrict__ b1,
                float* __restrict__ P, int M) {
    extern __shared__ __nv_bfloat16 smem[];
    __nv_bfloat16* Ahi = smem;                 // 128*40 = 5120
    __nv_bfloat16* Alo = smem + 5120;          // 5120
    __nv_bfloat16* Bhi = smem + 10240;         // 64*40 = 2560
    __nv_bfloat16* Blo = smem + 12800;         // 2560
    __nv_bfloat16* Hs  = smem + 15360;         // 128*136 = 17408
    __nv_bfloat16* Wfs = smem + 32768;         // 64*136 = 8704  (total 41472)

    int tid = threadIdx.x;
    int bm = blockIdx.x * 128;
    int wid = tid >> 5;
    int lane = tid & 31;
    int wm = wid >> 1;          // 0..3 : 32-row slab
    int wn = wid & 1;           // 0..1 : 32-col slab

    float acc2[2][4][4];
    #pragma unroll
    for (int i = 0; i < 2; i++)
        #pragma unroll
        for (int j = 0; j < 4; j++)
            #pragma unroll
            for (int v = 0; v < 4; v++) acc2[i][j][v] = 0.0f;

    for (int nt = 0; nt < 4; nt++) {
        // ---------------- phase A ----------------
        float acc[2][4][4];
        #pragma unroll
        for (int i = 0; i < 2; i++)
            #pragma unroll
            for (int j = 0; j < 4; j++)
                #pragma unroll
                for (int v = 0; v < 4; v++) acc[i][j][v] = 0.0f;

        for (int kk = 0; kk < FF; kk += 32) {
            // stage A hi+lo: 128 rows x 32 halves each
            #pragma unroll
            for (int it = 0; it < 2; it++) {
                int idx = tid + it * 256;
                int r = idx >> 2;
                int q = idx & 3;
                int m = bm + r;
                uint4 vh = make_uint4(0u, 0u, 0u, 0u);
                uint4 vl = make_uint4(0u, 0u, 0u, 0u);
                if (m < M) {
                    const __nv_bfloat16* base = &A[(size_t)m * (2 * FF) + kk + q * 8];
                    vh = *(const uint4*)base;
                    vl = *(const uint4*)(base + FF);
                }
                *(uint4*)&Ahi[r * ATP + q * 8] = vh;
                *(uint4*)&Alo[r * ATP + q * 8] = vl;
            }
            // stage W1 hi+lo: 64 rows x 32 halves each
            {
                int r = tid >> 2;
                int q = tid & 3;
                const __nv_bfloat16* base =
                    &W1s[(size_t)(nt * 64 + r) * (2 * FF) + kk + q * 8];
                *(uint4*)&Bhi[r * ATP + q * 8] = *(const uint4*)base;
                *(uint4*)&Blo[r * ATP + q * 8] = *(const uint4*)(base + FF);
            }
            __syncthreads();

            #pragma unroll
            for (int ks = 0; ks < 2; ks++) {
                int acol = ks * 16 + (lane >> 4) * 8;
                uint32_t ah[2][4], al[2][4];
                #pragma unroll
                for (int mi = 0; mi < 2; mi++) {
                    int row = wm * 32 + mi * 16 + (lane & 15);
                    ldmx4(ah[mi], &Ahi[row * ATP + acol]);
                    ldmx4(al[mi], &Alo[row * ATP + acol]);
                }
                uint32_t bh[2][4], bl[2][4];
                #pragma unroll
                for (int pr = 0; pr < 2; pr++) {
                    int row = wn * 32 + pr * 16 + (lane & 15);
                    ldmx4(bh[pr], &Bhi[row * ATP + acol]);
                    ldmx4(bl[pr], &Blo[row * ATP + acol]);
                }
                #pragma unroll
                for (int mi = 0; mi < 2; mi++)
                    #pragma unroll
                    for (int ni = 0; ni < 4; ni++) {
                        uint32_t bb[2];
                        // hi * hi
                        bb[0] = bh[ni >> 1][ni & 1];
                        bb[1] = bh[ni >> 1][(ni & 1) + 2];
                        mma16816(acc[mi][ni], ah[mi], bb);
                        // lo * hi
                        mma16816(acc[mi][ni], al[mi], bb);
                        // hi * lo
                        bb[0] = bl[ni >> 1][ni & 1];
                        bb[1] = bl[ni >> 1][(ni & 1) + 2];
                        mma16816(acc[mi][ni], ah[mi], bb);
                    }
            }
            __syncthreads();
        }

        // epilogue A: bias + relu + split -> Hs [hi(64)|lo(64)] stride HSTR
        #pragma unroll
        for (int mi = 0; mi < 2; mi++)
            #pragma unroll
            for (int ni = 0; ni < 4; ni++) {
                int row0 = wm * 32 + mi * 16 + (lane >> 2);
                int col0 = wn * 32 + ni * 8 + 2 * (lane & 3);
                int gc = nt * 64 + col0;
                float bv0 = b1[gc];
                float bv1 = b1[gc + 1];
                #pragma unroll
                for (int half = 0; half < 2; half++) {
                    int row = row0 + half * 8;
                    float a0 = acc[mi][ni][half * 2 + 0] + bv0;
                    float a1 = acc[mi][ni][half * 2 + 1] + bv1;
                    a0 = fmaxf(a0, 0.0f);
                    a1 = fmaxf(a1, 0.0f);
                    __nv_bfloat16 h0 = __float2bfloat16(a0);
                    __nv_bfloat16 h1 = __float2bfloat16(a1);
                    __nv_bfloat162 hip; hip.x = h0; hip.y = h1;
                    __nv_bfloat162 lop;
                    lop.x = __float2bfloat16(a0 - __bfloat162float(h0));
                    lop.y = __float2bfloat16(a1 - __bfloat162float(h1));
                    *(__nv_bfloat162*)&Hs[row * HSTR + col0]      = hip;
                    *(__nv_bfloat162*)&Hs[row * HSTR + 64 + col0] = lop;
                }
            }

        // stage Wf chunk: 64 rows x [hi64|lo64] -> Wfs stride HSTR
        for (int idx = tid; idx < 64 * 16; idx += 256) {
            int r = idx >> 4;
            int sub = idx & 15;
            int part = sub >> 3;            // 0=hi, 1=lo
            int q = sub & 7;
            uint4 v = *(const uint4*)&Wf16[(size_t)r * (2 * HH) + part * HH + nt * 64 + q * 8];
            *(uint4*)&Wfs[r * HSTR + part * 64 + q * 8] = v;
        }
        __syncthreads();

        // ---------------- phase B: p += Hs' (K=64, logical 192) x Wfs'^T ---
        for (int k0 = 0; k0 < 3 * 64; k0 += 16) {
            int seg = k0 >> 6;
            int kk = k0 & 63;
            int aoff = (seg == 2 ? 64 : 0) + kk;
            int boff = (seg == 1 ? 64 : 0) + kk;

            uint32_t afr[2][4];
            #pragma unroll
            for (int mi = 0; mi < 2; mi++) {
                int row = wm * 32 + mi * 16 + (lane & 15);
                ldmx4(afr[mi], &Hs[row * HSTR + aoff + (lane >> 4) * 8]);
            }
            uint32_t bfr[2][4];
            #pragma unroll
            for (int pr = 0; pr < 2; pr++) {
                int row = wn * 32 + pr * 16 + (lane & 15);
                ldmx4(bfr[pr], &Wfs[row * HSTR + boff + (lane >> 4) * 8]);
            }
            #pragma unroll
            for (int mi = 0; mi < 2; mi++)
                #pragma unroll
                for (int ni = 0; ni < 4; ni++) {
                    uint32_t bb[2];
                    bb[0] = bfr[ni >> 1][ni & 1];
                    bb[1] = bfr[ni >> 1][(ni & 1) + 2];
                    mma16816(acc2[mi][ni], afr[mi], bb);
                }
        }
        __syncthreads();   // protect Hs/Wfs before next nt overwrites
    }

    // epilogue: write p (stride PSTR, cols < CC, rows < M)
    #pragma unroll
    for (int mi = 0; mi < 2; mi++)
        #pragma unroll
        for (int ni = 0; ni < 4; ni++) {
            int col0 = wn * 32 + ni * 8 + 2 * (lane & 3);
            if (col0 >= CC) continue;
            int row0 = bm + wm * 32 + mi * 16 + (lane >> 2);
            if (row0 < M)
                *(float2*)&P[(size_t)row0 * PSTR + col0] =
                    make_float2(acc2[mi][ni][0], acc2[mi][ni][1]);
            if (row0 + 8 < M)
                *(float2*)&P[(size_t)(row0 + 8) * PSTR + col0] =
                    make_float2(acc2[mi][ni][2], acc2[mi][ni][3]);
        }
}

// ---------------- final aggregation at C=40: warp per node ------------------
__global__ __launch_bounds__(256)
void aggregate_final_kernel(float* __restrict__ out) {
    int node = blockIdx.x * 8 + (threadIdx.x >> 5);
    int lane = threadIdx.x & 31;
    if (node >= NN) return;

    const float* __restrict__ p = g_p;
    int start = g_rowptr[node];
    int d = g_deg[node];
    float di = g_dinv[node];

    float acc0 = 0.0f, acc1 = 0.0f;
    #pragma unroll 8
    for (int j = 0; j < d; j++) {
        int s = g_csrc[start + j];        // uniform across warp -> broadcast
        float w = g_cw[start + j];
        const float* row = &p[(size_t)s * PSTR];
        acc0 += w * row[lane];
        if (lane < CC - 32) acc1 += w * row[32 + lane];
    }

    const float* self = &p[(size_t)node * PSTR];
    float v0 = di * acc0 + di * di * self[lane] + g_biasf[lane];
    out[(size_t)node * CC + lane] = v0;
    if (lane < CC - 32) {
        float v1 = di * acc1 + di * di * self[32 + lane] + g_biasf[32 + lane];
        out[(size_t)node * CC + 32 + lane] = v1;
    }
}

// ---------------- launch ----------------------------------------------------
extern "C" void kernel_launch(void* const* d_in, const int* in_sizes, int n_in,
                              void* d_out, int out_size) {
    const float* x    = (const float*)d_in[0];
    const int*   ei   = (const int*)d_in[1];
    const float* W1   = (const float*)d_in[2];
    const float* b1   = (const float*)d_in[3];
    const float* W2   = (const float*)d_in[4];
    const float* b2   = (const float*)d_in[5];
    const float* Wout = (const float*)d_in[6];
    const float* bout = (const float*)d_in[7];
    float* out = (float*)d_out;

    const int* src = ei;         // edge_index[0]
    const int* dst = ei + EE;    // edge_index[1]

    __nv_bfloat16* a16;  cudaGetSymbolAddress((void**)&a16, g_a16);
    __nv_bfloat16* w16;  cudaGetSymbolAddress((void**)&w16, g_w16);
    __nv_bfloat16* wf16; cudaGetSymbolAddress((void**)&wf16, g_wf16);
    float* pbuf; cudaGetSymbolAddress((void**)&pbuf, g_p);

    cudaFuncSetAttribute(b2b_kernel, cudaFuncAttributeMaxDynamicSharedMemorySize,
                         41472 * (int)sizeof(__nv_bfloat16));

    // ---- prep: weights + zero deg (one kernel) ----
    prep_kernel<<<365, 256>>>(W1, W2, Wout, b2, bout);

    // ---- CSR build ----
    count_deg_kernel<<<(EE + 255) / 256, 256>>>(dst);
    scan_kernel<<<1, 1024>>>();                         // rowptr+cursor+dinv, one pass
    fill_csr_kernel<<<(EE + 255) / 256, 256>>>(src, dst);

    // ---- agg(x) -> split a16 ----
    aggregate_split_kernel<<<NN, FF>>>(x);

    // ---- fused B2B: p = relu(a16 @ W1'^T + b1) @ Wf'^T ----
    b2b_kernel<<<(NN + 127) / 128, 256, 41472 * sizeof(__nv_bfloat16)>>>(
        a16, w16, wf16, b1, pbuf, NN);

    // ---- final aggregation at C=40 -> out ----
    aggregate_final_kernel<<<(NN + 7) / 8, 256>>>(out);
}

// round 12
// speedup vs baseline: 1.1715x; 1.1715x over previous
#include <cuda_runtime.h>
#include <cuda_bf16.h>
#include <cstdint>

#define NN 50000
#define EE 800000
#define FF 128
#define HH 256
#define CC 40
#define PSTR 64                   // padded p row stride
#define NB ((NN + 1023) / 1024)   // 49 scan blocks

// ---------------- scratch (device globals; no runtime allocation) ----------
__device__ __nv_bfloat16 g_a16[(size_t)NN * 2 * FF];   // split agg(x)  [N,256]=[hi|lo]
__device__ __nv_bfloat16 g_w16[(size_t)HH * 2 * FF];   // split W1 [256][hi128|lo128]
__device__ __nv_bfloat16 g_wf16[(size_t)64 * 2 * HH];  // split Wf [64][hi256|lo256]
__device__ float g_p[(size_t)NN * PSTR];               // pre-agg logits [N,40] pad 64
__device__ float g_biasf[CC];                          // fused bias
__device__ int   g_deg[NN];
__device__ float g_dinv[NN];
__device__ int   g_rowptr[NN];
__device__ int   g_cursor[NN];
__device__ int   g_partials[64];
__device__ int   g_csrc[EE];
__device__ float g_cw[EE];                             // per-edge dinv[src]

// ---------------- combined prep ---------------------------------------------
// blocks 0..127   : split W1 (256x128) -> g_w16 rows [hi128|lo128]
// blocks 128..167 : c = b-128: Wf row c = Wout[c]@W2 (fp32), split -> g_wf16;
//                   biasf[c] = bout[c] + Wout[c]@b2
// block 168       : zero-pad g_wf16 rows 40..63
// blocks 169..364 : zero g_deg
__global__ void prep_kernel(const float* __restrict__ W1, const float* __restrict__ W2,
                            const float* __restrict__ Wout, const float* __restrict__ b2,
                            const float* __restrict__ bout) {
    __shared__ float sh[256];
    int b = blockIdx.x;
    int t = threadIdx.x;
    if (b < 128) {
        int idx = b * 256 + t;
        int n = idx >> 7;            // row 0..255
        int k = idx & 127;
        float v = W1[(size_t)n * FF + k];
        __nv_bfloat16 hi = __float2bfloat16(v);
        __nv_bfloat16 lo = __float2bfloat16(v - __bfloat162float(hi));
        g_w16[(size_t)n * (2 * FF) + k]      = hi;
        g_w16[(size_t)n * (2 * FF) + FF + k] = lo;
    } else if (b < 168) {
        int c = b - 128;             // 0..39
        float wc = Wout[(size_t)c * HH + t];
        float acc = 0.0f;
        #pragma unroll 4
        for (int o = 0; o < HH; o++)
            acc += Wout[(size_t)c * HH + o] * W2[(size_t)o * HH + t];
        __nv_bfloat16 hi = __float2bfloat16(acc);
        __nv_bfloat16 lo = __float2bfloat16(acc - __bfloat162float(hi));
        g_wf16[(size_t)c * (2 * HH) + t]      = hi;
        g_wf16[(size_t)c * (2 * HH) + HH + t] = lo;
        sh[t] = wc * b2[t];
        __syncthreads();
        for (int off = 128; off > 0; off >>= 1) {
            if (t < off) sh[t] += sh[t + off];
            __syncthreads();
        }
        if (t == 0) g_biasf[c] = bout[c] + sh[0];
    } else if (b == 168) {
        __nv_bfloat16 z = __float2bfloat16(0.0f);
        for (int idx = t; idx < 24 * 2 * HH; idx += 256)
            g_wf16[(size_t)40 * (2 * HH) + idx] = z;
    } else {
        int i = (b - 169) * 256 + t;
        if (i < NN) g_deg[i] = 0;
    }
}

// ---------------- CSR build ------------------------------------------------
__global__ void count_deg_kernel(const int* __restrict__ dst) {
    int e = blockIdx.x * blockDim.x + threadIdx.x;
    if (e < EE) atomicAdd(&g_deg[dst[e]], 1);
}

__global__ void scan_blocks_kernel() {
    __shared__ int sh[1024];
    int t = threadIdx.x;
    int i = blockIdx.x * 1024 + t;
    int v = (i < NN) ? g_deg[i] : 0;
    if (i < NN) g_dinv[i] = rsqrtf((float)v + 1.0f);   // fused dinv
    sh[t] = v;
    __syncthreads();
    #pragma unroll
    for (int off = 1; off < 1024; off <<= 1) {
        int add = (t >= off) ? sh[t - off] : 0;
        __syncthreads();
        sh[t] += add;
        __syncthreads();
    }
    if (i < NN) g_rowptr[i] = sh[t] - v;   // exclusive prefix within block
    if (t == 1023) g_partials[blockIdx.x] = sh[1023];   // raw block sums
}

// add block-prefix of partials inline (warp-reduce over <=49 raw sums)
__global__ void add_offsets_kernel() {
    __shared__ int s_pref;
    int i = blockIdx.x * blockDim.x + threadIdx.x;
    int grp = (blockIdx.x * 256) >> 10;   // constant per 256-thread block
    if (threadIdx.x < 32) {
        int acc = 0;
        for (int b = threadIdx.x; b < grp; b += 32) acc += g_partials[b];
        #pragma unroll
        for (int off = 16; off; off >>= 1) acc += __shfl_xor_sync(~0u, acc, off);
        if (threadIdx.x == 0) s_pref = acc;
    }
    __syncthreads();
    if (i < NN) {
        int v = g_rowptr[i] + s_pref;
        g_rowptr[i] = v;
        g_cursor[i] = v;
    }
}

__global__ void fill_csr_kernel(const int* __restrict__ src, const int* __restrict__ dst) {
    int e = blockIdx.x * blockDim.x + threadIdx.x;
    if (e < EE) {
        int s = src[e];
        int pos = atomicAdd(&g_cursor[dst[e]], 1);
        g_csrc[pos] = s;
        g_cw[pos] = g_dinv[s];
    }
}

// ---------------- agg(x) with split-bf16 output -----------------------------
__global__ __launch_bounds__(FF)
void aggregate_split_kernel(const float* __restrict__ h) {
    int i = blockIdx.x;
    int c = threadIdx.x;
    __shared__ int   s_src[FF];
    __shared__ float s_w[FF];

    int start = g_rowptr[i];
    int d = g_deg[i];
    float di = g_dinv[i];
    float acc = 0.0f;

    if (d <= FF) {
        if (c < d) {
            s_src[c] = g_csrc[start + c];
            s_w[c] = g_cw[start + c];
        }
        __syncthreads();
        #pragma unroll 4
        for (int j = 0; j < d; j++)
            acc += s_w[j] * h[(size_t)s_src[j] * FF + c];
    } else {
        for (int base = 0; base < d; base += FF) {
            int n = d - base;
            if (n > FF) n = FF;
            __syncthreads();
            if (c < n) {
                s_src[c] = g_csrc[start + base + c];
                s_w[c] = g_cw[start + base + c];
            }
            __syncthreads();
            #pragma unroll 4
            for (int j = 0; j < n; j++)
                acc += s_w[j] * h[(size_t)s_src[j] * FF + c];
        }
    }

    float v = di * acc + di * di * h[(size_t)i * FF + c];
    __nv_bfloat16 hi = __float2bfloat16(v);
    __nv_bfloat16 lo = __float2bfloat16(v - __bfloat162float(hi));
    size_t b = (size_t)i * (2 * FF);
    g_a16[b + c]      = hi;
    g_a16[b + FF + c] = lo;
}

// ---------------- mma helpers -----------------------------------------------
__device__ __forceinline__ void ldmx4(uint32_t* r, const __nv_bfloat16* p) {
    uint32_t addr = (uint32_t)__cvta_generic_to_shared(p);
    asm volatile("ldmatrix.sync.aligned.m8n8.x4.shared.b16 {%0,%1,%2,%3}, [%4];"
                 : "=r"(r[0]), "=r"(r[1]), "=r"(r[2]), "=r"(r[3]) : "r"(addr));
}

__device__ __forceinline__ void mma16816(float* d, const uint32_t* a, const uint32_t* b) {
    asm volatile(
        "mma.sync.aligned.m16n8k16.row.col.f32.bf16.bf16.f32 "
        "{%0,%1,%2,%3}, {%4,%5,%6,%7}, {%8,%9}, {%0,%1,%2,%3};"
        : "+f"(d[0]), "+f"(d[1]), "+f"(d[2]), "+f"(d[3])
        : "r"(a[0]), "r"(a[1]), "r"(a[2]), "r"(a[3]), "r"(b[0]), "r"(b[1]));
}

// ---------------- B2B kernel: p = relu(a16*W1'^T+b1) * Wf'^T ----------------
#define HSTR 136
#define ATP 40

__global__ __launch_bounds__(256, 2)
void b2b_kernel(const __nv_bfloat16* __restrict__ A,
                const __nv_bfloat16* __restrict__ W1s,
                const __nv_bfloat16* __restrict__ Wf16,
                const float* __restrict__ b1,
                float* __restrict__ P, int M) {
    extern __shared__ __nv_bfloat16 smem[];
    __nv_bfloat16* Ahi = smem;                 // 128*40 = 5120
    __nv_bfloat16* Alo = smem + 5120;          // 5120
    __nv_bfloat16* Bhi = smem + 10240;         // 64*40 = 2560
    __nv_bfloat16* Blo = smem + 12800;         // 2560
    __nv_bfloat16* Hs  = smem + 15360;         // 128*136 = 17408
    __nv_bfloat16* Wfs = smem + 32768;         // 64*136 = 8704  (total 41472)

    int tid = threadIdx.x;
    int bm = blockIdx.x * 128;
    int wid = tid >> 5;
    int lane = tid & 31;
    int wm = wid >> 1;          // 0..3 : 32-row slab
    int wn = wid & 1;           // 0..1 : 32-col slab

    float acc2[2][4][4];
    #pragma unroll
    for (int i = 0; i < 2; i++)
        #pragma unroll
        for (int j = 0; j < 4; j++)
            #pragma unroll
            for (int v = 0; v < 4; v++) acc2[i][j][v] = 0.0f;

    for (int nt = 0; nt < 4; nt++) {
        // ---------------- phase A ----------------
        float acc[2][4][4];
        #pragma unroll
        for (int i = 0; i < 2; i++)
            #pragma unroll
            for (int j = 0; j < 4; j++)
                #pragma unroll
                for (int v = 0; v < 4; v++) acc[i][j][v] = 0.0f;

        for (int kk = 0; kk < FF; kk += 32) {
            // stage A hi+lo: 128 rows x 32 halves each
            #pragma unroll
            for (int it = 0; it < 2; it++) {
                int idx = tid + it * 256;
                int r = idx >> 2;
                int q = idx & 3;
                int m = bm + r;
                uint4 vh = make_uint4(0u, 0u, 0u, 0u);
                uint4 vl = make_uint4(0u, 0u, 0u, 0u);
                if (m < M) {
                    const __nv_bfloat16* base = &A[(size_t)m * (2 * FF) + kk + q * 8];
                    vh = *(const uint4*)base;
                    vl = *(const uint4*)(base + FF);
                }
                *(uint4*)&Ahi[r * ATP + q * 8] = vh;
                *(uint4*)&Alo[r * ATP + q * 8] = vl;
            }
            // stage W1 hi+lo: 64 rows x 32 halves each
            {
                int r = tid >> 2;
                int q = tid & 3;
                const __nv_bfloat16* base =
                    &W1s[(size_t)(nt * 64 + r) * (2 * FF) + kk + q * 8];
                *(uint4*)&Bhi[r * ATP + q * 8] = *(const uint4*)base;
                *(uint4*)&Blo[r * ATP + q * 8] = *(const uint4*)(base + FF);
            }
            __syncthreads();

            #pragma unroll
            for (int ks = 0; ks < 2; ks++) {
                int acol = ks * 16 + (lane >> 4) * 8;
                uint32_t ah[2][4], al[2][4];
                #pragma unroll
                for (int mi = 0; mi < 2; mi++) {
                    int row = wm * 32 + mi * 16 + (lane & 15);
                    ldmx4(ah[mi], &Ahi[row * ATP + acol]);
                    ldmx4(al[mi], &Alo[row * ATP + acol]);
                }
                uint32_t bh[2][4], bl[2][4];
                #pragma unroll
                for (int pr = 0; pr < 2; pr++) {
                    int row = wn * 32 + pr * 16 + (lane & 15);
                    ldmx4(bh[pr], &Bhi[row * ATP + acol]);
                    ldmx4(bl[pr], &Blo[row * ATP + acol]);
                }
                #pragma unroll
                for (int mi = 0; mi < 2; mi++)
                    #pragma unroll
                    for (int ni = 0; ni < 4; ni++) {
                        uint32_t bb[2];
                        // hi * hi
                        bb[0] = bh[ni >> 1][ni & 1];
                        bb[1] = bh[ni >> 1][(ni & 1) + 2];
                        mma16816(acc[mi][ni], ah[mi], bb);
                        // lo * hi
                        mma16816(acc[mi][ni], al[mi], bb);
                        // hi * lo
                        bb[0] = bl[ni >> 1][ni & 1];
                        bb[1] = bl[ni >> 1][(ni & 1) + 2];
                        mma16816(acc[mi][ni], ah[mi], bb);
                    }
            }
            __syncthreads();
        }

        // epilogue A: bias + relu + split -> Hs [hi(64)|lo(64)] stride HSTR
        #pragma unroll
        for (int mi = 0; mi < 2; mi++)
            #pragma unroll
            for (int ni = 0; ni < 4; ni++) {
                int row0 = wm * 32 + mi * 16 + (lane >> 2);
                int col0 = wn * 32 + ni * 8 + 2 * (lane & 3);
                int gc = nt * 64 + col0;
                float bv0 = b1[gc];
                float bv1 = b1[gc + 1];
                #pragma unroll
                for (int half = 0; half < 2; half++) {
                    int row = row0 + half * 8;
                    float a0 = acc[mi][ni][half * 2 + 0] + bv0;
                    float a1 = acc[mi][ni][half * 2 + 1] + bv1;
                    a0 = fmaxf(a0, 0.0f);
                    a1 = fmaxf(a1, 0.0f);
                    __nv_bfloat16 h0 = __float2bfloat16(a0);
                    __nv_bfloat16 h1 = __float2bfloat16(a1);
                    __nv_bfloat162 hip; hip.x = h0; hip.y = h1;
                    __nv_bfloat162 lop;
                    lop.x = __float2bfloat16(a0 - __bfloat162float(h0));
                    lop.y = __float2bfloat16(a1 - __bfloat162float(h1));
                    *(__nv_bfloat162*)&Hs[row * HSTR + col0]      = hip;
                    *(__nv_bfloat162*)&Hs[row * HSTR + 64 + col0] = lop;
                }
            }

        // stage Wf chunk: 64 rows x [hi64|lo64] -> Wfs stride HSTR
        for (int idx = tid; idx < 64 * 16; idx += 256) {
            int r = idx >> 4;
            int sub = idx & 15;
            int part = sub >> 3;            // 0=hi, 1=lo
            int q = sub & 7;
            uint4 v = *(const uint4*)&Wf16[(size_t)r * (2 * HH) + part * HH + nt * 64 + q * 8];
            *(uint4*)&Wfs[r * HSTR + part * 64 + q * 8] = v;
        }
        __syncthreads();

        // ---------------- phase B: p += Hs' (K=64, logical 192) x Wfs'^T ---
        for (int k0 = 0; k0 < 3 * 64; k0 += 16) {
            int seg = k0 >> 6;
            int kk = k0 & 63;
            int aoff = (seg == 2 ? 64 : 0) + kk;
            int boff = (seg == 1 ? 64 : 0) + kk;

            uint32_t afr[2][4];
            #pragma unroll
            for (int mi = 0; mi < 2; mi++) {
                int row = wm * 32 + mi * 16 + (lane & 15);
                ldmx4(afr[mi], &Hs[row * HSTR + aoff + (lane >> 4) * 8]);
            }
            uint32_t bfr[2][4];
            #pragma unroll
            for (int pr = 0; pr < 2; pr++) {
                int row = wn * 32 + pr * 16 + (lane & 15);
                ldmx4(bfr[pr], &Wfs[row * HSTR + boff + (lane >> 4) * 8]);
            }
            #pragma unroll
            for (int mi = 0; mi < 2; mi++)
                #pragma unroll
                for (int ni = 0; ni < 4; ni++) {
                    uint32_t bb[2];
                    bb[0] = bfr[ni >> 1][ni & 1];
                    bb[1] = bfr[ni >> 1][(ni & 1) + 2];
                    mma16816(acc2[mi][ni], afr[mi], bb);
                }
        }
        __syncthreads();   // protect Hs/Wfs before next nt overwrites
    }

    // epilogue: write p (stride PSTR, cols < CC, rows < M)
    #pragma unroll
    for (int mi = 0; mi < 2; mi++)
        #pragma unroll
        for (int ni = 0; ni < 4; ni++) {
            int col0 = wn * 32 + ni * 8 + 2 * (lane & 3);
            if (col0 >= CC) continue;
            int row0 = bm + wm * 32 + mi * 16 + (lane >> 2);
            if (row0 < M)
                *(float2*)&P[(size_t)row0 * PSTR + col0] =
                    make_float2(acc2[mi][ni][0], acc2[mi][ni][1]);
            if (row0 + 8 < M)
                *(float2*)&P[(size_t)(row0 + 8) * PSTR + col0] =
                    make_float2(acc2[mi][ni][2], acc2[mi][ni][3]);
        }
}

// ---------------- final aggregation at C=40: warp per node ------------------
__global__ __launch_bounds__(256)
void aggregate_final_kernel(float* __restrict__ out) {
    int node = blockIdx.x * 8 + (threadIdx.x >> 5);
    int lane = threadIdx.x & 31;
    if (node >= NN) return;

    const float* __restrict__ p = g_p;
    int start = g_rowptr[node];
    int d = g_deg[node];
    float di = g_dinv[node];

    float acc0 = 0.0f, acc1 = 0.0f;
    #pragma unroll 4
    for (int j = 0; j < d; j++) {
        int s = g_csrc[start + j];        // uniform across warp -> broadcast
        float w = g_cw[start + j];
        const float* row = &p[(size_t)s * PSTR];
        acc0 += w * row[lane];
        if (lane < CC - 32) acc1 += w * row[32 + lane];
    }

    const float* self = &p[(size_t)node * PSTR];
    float v0 = di * acc0 + di * di * self[lane] + g_biasf[lane];
    out[(size_t)node * CC + lane] = v0;
    if (lane < CC - 32) {
        float v1 = di * acc1 + di * di * self[32 + lane] + g_biasf[32 + lane];
        out[(size_t)node * CC + 32 + lane] = v1;
    }
}

// ---------------- launch ----------------------------------------------------
extern "C" void kernel_launch(void* const* d_in, const int* in_sizes, int n_in,
                              void* d_out, int out_size) {
    const float* x    = (const float*)d_in[0];
    const int*   ei   = (const int*)d_in[1];
    const float* W1   = (const float*)d_in[2];
    const float* b1   = (const float*)d_in[3];
    const float* W2   = (const float*)d_in[4];
    const float* b2   = (const float*)d_in[5];
    const float* Wout = (const float*)d_in[6];
    const float* bout = (const float*)d_in[7];
    float* out = (float*)d_out;

    const int* src = ei;         // edge_index[0]
    const int* dst = ei + EE;    // edge_index[1]

    __nv_bfloat16* a16;  cudaGetSymbolAddress((void**)&a16, g_a16);
    __nv_bfloat16* w16;  cudaGetSymbolAddress((void**)&w16, g_w16);
    __nv_bfloat16* wf16; cudaGetSymbolAddress((void**)&wf16, g_wf16);
    float* pbuf; cudaGetSymbolAddress((void**)&pbuf, g_p);

    cudaFuncSetAttribute(b2b_kernel, cudaFuncAttributeMaxDynamicSharedMemorySize,
                         41472 * (int)sizeof(__nv_bfloat16));

    // ---- prep: weights + zero deg (one kernel) ----
    prep_kernel<<<365, 256>>>(W1, W2, Wout, b2, bout);

    // ---- CSR build ----
    count_deg_kernel<<<(EE + 255) / 256, 256>>>(dst);
    scan_blocks_kernel<<<NB, 1024>>>();          // also computes dinv
    add_offsets_kernel<<<(NN + 255) / 256, 256>>>();   // inline partials prefix
    fill_csr_kernel<<<(EE + 255) / 256, 256>>>(src, dst);

    // ---- agg(x) -> split a16 ----
    aggregate_split_kernel<<<NN, FF>>>(x);

    // ---- fused B2B: p = relu(a16 @ W1'^T + b1) @ Wf'^T ----
    b2b_kernel<<<(NN + 127) / 128, 256, 41472 * sizeof(__nv_bfloat16)>>>(
        a16, w16, wf16, b1, pbuf, NN);

    // ---- final aggregation at C=40 -> out ----
    aggregate_final_kernel<<<(NN + 7) / 8, 256>>>(out);
}

// round 13
// speedup vs baseline: 1.2056x; 1.0291x over previous
#include <cuda_runtime.h>
#include <cuda_bf16.h>
#include <cstdint>

#define NN 50000
#define EE 800000
#define FF 128
#define HH 256
#define CC 40
#define PSTR 64                   // padded p row stride
#define NB ((NN + 1023) / 1024)   // 49 scan blocks

// ---------------- scratch (device globals; no runtime allocation) ----------
__device__ __nv_bfloat16 g_a16[(size_t)NN * 2 * FF];   // split agg(x)  [N,256]=[hi|lo]
__device__ __nv_bfloat16 g_w16[(size_t)HH * 2 * FF];   // split W1 [256][hi128|lo128]
__device__ __nv_bfloat16 g_wf16[(size_t)64 * 2 * HH];  // split Wf [64][hi256|lo256]
__device__ float g_p[(size_t)NN * PSTR];               // pre-agg logits [N,40] pad 64
__device__ float g_biasf[CC];                          // fused bias
__device__ int   g_deg[NN];
__device__ float g_dinv[NN];
__device__ int   g_rowptr[NN];
__device__ int   g_cursor[NN];
__device__ int   g_partials[64];
__device__ int2  g_epack[EE];                          // {src, dinv[src] bits}

// ---------------- combined prep ---------------------------------------------
// blocks 0..127   : split W1 (256x128) -> g_w16 rows [hi128|lo128]
// blocks 128..167 : c = b-128: Wf row c = Wout[c]@W2 (fp32), split -> g_wf16;
//                   biasf[c] = bout[c] + Wout[c]@b2
// block 168       : zero-pad g_wf16 rows 40..63
// blocks 169..364 : zero g_deg
__global__ void prep_kernel(const float* __restrict__ W1, const float* __restrict__ W2,
                            const float* __restrict__ Wout, const float* __restrict__ b2,
                            const float* __restrict__ bout) {
    __shared__ float sh[256];
    int b = blockIdx.x;
    int t = threadIdx.x;
    if (b < 128) {
        int idx = b * 256 + t;
        int n = idx >> 7;            // row 0..255
        int k = idx & 127;
        float v = W1[(size_t)n * FF + k];
        __nv_bfloat16 hi = __float2bfloat16(v);
        __nv_bfloat16 lo = __float2bfloat16(v - __bfloat162float(hi));
        g_w16[(size_t)n * (2 * FF) + k]      = hi;
        g_w16[(size_t)n * (2 * FF) + FF + k] = lo;
    } else if (b < 168) {
        int c = b - 128;             // 0..39
        float wc = Wout[(size_t)c * HH + t];
        float acc = 0.0f;
        #pragma unroll 4
        for (int o = 0; o < HH; o++)
            acc += Wout[(size_t)c * HH + o] * W2[(size_t)o * HH + t];
        __nv_bfloat16 hi = __float2bfloat16(acc);
        __nv_bfloat16 lo = __float2bfloat16(acc - __bfloat162float(hi));
        g_wf16[(size_t)c * (2 * HH) + t]      = hi;
        g_wf16[(size_t)c * (2 * HH) + HH + t] = lo;
        sh[t] = wc * b2[t];
        __syncthreads();
        for (int off = 128; off > 0; off >>= 1) {
            if (t < off) sh[t] += sh[t + off];
            __syncthreads();
        }
        if (t == 0) g_biasf[c] = bout[c] + sh[0];
    } else if (b == 168) {
        __nv_bfloat16 z = __float2bfloat16(0.0f);
        for (int idx = t; idx < 24 * 2 * HH; idx += 256)
            g_wf16[(size_t)40 * (2 * HH) + idx] = z;
    } else {
        int i = (b - 169) * 256 + t;
        if (i < NN) g_deg[i] = 0;
    }
}

// ---------------- CSR build ------------------------------------------------
__global__ void count_deg_kernel(const int* __restrict__ dst) {
    int e = blockIdx.x * blockDim.x + threadIdx.x;
    if (e < EE) atomicAdd(&g_deg[dst[e]], 1);
}

__global__ void scan_blocks_kernel() {
    __shared__ int sh[1024];
    int t = threadIdx.x;
    int i = blockIdx.x * 1024 + t;
    int v = (i < NN) ? g_deg[i] : 0;
    if (i < NN) g_dinv[i] = rsqrtf((float)v + 1.0f);   // fused dinv
    sh[t] = v;
    __syncthreads();
    #pragma unroll
    for (int off = 1; off < 1024; off <<= 1) {
        int add = (t >= off) ? sh[t - off] : 0;
        __syncthreads();
        sh[t] += add;
        __syncthreads();
    }
    if (i < NN) g_rowptr[i] = sh[t] - v;   // exclusive prefix within block
    if (t == 1023) g_partials[blockIdx.x] = sh[1023];   // raw block sums
}

// add block-prefix of partials inline (warp-reduce over <=49 raw sums)
__global__ void add_offsets_kernel() {
    __shared__ int s_pref;
    int i = blockIdx.x * blockDim.x + threadIdx.x;
    int grp = (blockIdx.x * 256) >> 10;   // constant per 256-thread block
    if (threadIdx.x < 32) {
        int acc = 0;
        for (int b = threadIdx.x; b < grp; b += 32) acc += g_partials[b];
        #pragma unroll
        for (int off = 16; off; off >>= 1) acc += __shfl_xor_sync(~0u, acc, off);
        if (threadIdx.x == 0) s_pref = acc;
    }
    __syncthreads();
    if (i < NN) {
        int v = g_rowptr[i] + s_pref;
        g_rowptr[i] = v;
        g_cursor[i] = v;
    }
}

__global__ void fill_csr_kernel(const int* __restrict__ src, const int* __restrict__ dst) {
    int e = blockIdx.x * blockDim.x + threadIdx.x;
    if (e < EE) {
        int s = src[e];
        int pos = atomicAdd(&g_cursor[dst[e]], 1);
        g_epack[pos] = make_int2(s, __float_as_int(g_dinv[s]));
    }
}

// ---------------- agg(x) with split-bf16 output -----------------------------
__global__ __launch_bounds__(FF)
void aggregate_split_kernel(const float* __restrict__ h) {
    int i = blockIdx.x;
    int c = threadIdx.x;
    __shared__ int2 s_e[FF];

    int start = g_rowptr[i];
    int d = g_deg[i];
    float di = g_dinv[i];
    float acc = 0.0f;

    if (d <= FF) {
        if (c < d) s_e[c] = g_epack[start + c];
        __syncthreads();
        #pragma unroll 4
        for (int j = 0; j < d; j++) {
            int2 e = s_e[j];
            acc += __int_as_float(e.y) * h[(size_t)e.x * FF + c];
        }
    } else {
        for (int base = 0; base < d; base += FF) {
            int n = d - base;
            if (n > FF) n = FF;
            __syncthreads();
            if (c < n) s_e[c] = g_epack[start + base + c];
            __syncthreads();
            #pragma unroll 4
            for (int j = 0; j < n; j++) {
                int2 e = s_e[j];
                acc += __int_as_float(e.y) * h[(size_t)e.x * FF + c];
            }
        }
    }

    float v = di * acc + di * di * h[(size_t)i * FF + c];
    __nv_bfloat16 hi = __float2bfloat16(v);
    __nv_bfloat16 lo = __float2bfloat16(v - __bfloat162float(hi));
    size_t b = (size_t)i * (2 * FF);
    g_a16[b + c]      = hi;
    g_a16[b + FF + c] = lo;
}

// ---------------- mma helpers -----------------------------------------------
__device__ __forceinline__ void ldmx4(uint32_t* r, const __nv_bfloat16* p) {
    uint32_t addr = (uint32_t)__cvta_generic_to_shared(p);
    asm volatile("ldmatrix.sync.aligned.m8n8.x4.shared.b16 {%0,%1,%2,%3}, [%4];"
                 : "=r"(r[0]), "=r"(r[1]), "=r"(r[2]), "=r"(r[3]) : "r"(addr));
}

__device__ __forceinline__ void mma16816(float* d, const uint32_t* a, const uint32_t* b) {
    asm volatile(
        "mma.sync.aligned.m16n8k16.row.col.f32.bf16.bf16.f32 "
        "{%0,%1,%2,%3}, {%4,%5,%6,%7}, {%8,%9}, {%0,%1,%2,%3};"
        : "+f"(d[0]), "+f"(d[1]), "+f"(d[2]), "+f"(d[3])
        : "r"(a[0]), "r"(a[1]), "r"(a[2]), "r"(a[3]), "r"(b[0]), "r"(b[1]));
}

// ---------------- B2B kernel: p = relu(a16*W1'^T+b1) * Wf'^T ----------------
#define HSTR 136
#define ATP 40

__global__ __launch_bounds__(256, 2)
void b2b_kernel(const __nv_bfloat16* __restrict__ A,
                const __nv_bfloat16* __restrict__ W1s,
                const __nv_bfloat16* __restrict__ Wf16,
                const float* __restrict__ b1,
                float* __restrict__ P, int M) {
    extern __shared__ __nv_bfloat16 smem[];
    __nv_bfloat16* Ahi = smem;                 // 128*40 = 5120
    __nv_bfloat16* Alo = smem + 5120;          // 5120
    __nv_bfloat16* Bhi = smem + 10240;         // 64*40 = 2560
    __nv_bfloat16* Blo = smem + 12800;         // 2560
    __nv_bfloat16* Hs  = smem + 15360;         // 128*136 = 17408
    __nv_bfloat16* Wfs = smem + 32768;         // 64*136 = 8704  (total 41472)

    int tid = threadIdx.x;
    int bm = blockIdx.x * 128;
    int wid = tid >> 5;
    int lane = tid & 31;
    int wm = wid >> 1;          // 0..3 : 32-row slab
    int wn = wid & 1;           // 0..1 : 32-col slab

    float acc2[2][4][4];
    #pragma unroll
    for (int i = 0; i < 2; i++)
        #pragma unroll
        for (int j = 0; j < 4; j++)
            #pragma unroll
            for (int v = 0; v < 4; v++) acc2[i][j][v] = 0.0f;

    for (int nt = 0; nt < 4; nt++) {
        // ---------------- phase A ----------------
        float acc[2][4][4];
        #pragma unroll
        for (int i = 0; i < 2; i++)
            #pragma unroll
            for (int j = 0; j < 4; j++)
                #pragma unroll
                for (int v = 0; v < 4; v++) acc[i][j][v] = 0.0f;

        for (int kk = 0; kk < FF; kk += 32) {
            // stage A hi+lo: 128 rows x 32 halves each
            #pragma unroll
            for (int it = 0; it < 2; it++) {
                int idx = tid + it * 256;
                int r = idx >> 2;
                int q = idx & 3;
                int m = bm + r;
                uint4 vh = make_uint4(0u, 0u, 0u, 0u);
                uint4 vl = make_uint4(0u, 0u, 0u, 0u);
                if (m < M) {
                    const __nv_bfloat16* base = &A[(size_t)m * (2 * FF) + kk + q * 8];
                    vh = *(const uint4*)base;
                    vl = *(const uint4*)(base + FF);
                }
                *(uint4*)&Ahi[r * ATP + q * 8] = vh;
                *(uint4*)&Alo[r * ATP + q * 8] = vl;
            }
            // stage W1 hi+lo: 64 rows x 32 halves each
            {
                int r = tid >> 2;
                int q = tid & 3;
                const __nv_bfloat16* base =
                    &W1s[(size_t)(nt * 64 + r) * (2 * FF) + kk + q * 8];
                *(uint4*)&Bhi[r * ATP + q * 8] = *(const uint4*)base;
                *(uint4*)&Blo[r * ATP + q * 8] = *(const uint4*)(base + FF);
            }
            __syncthreads();

            #pragma unroll
            for (int ks = 0; ks < 2; ks++) {
                int acol = ks * 16 + (lane >> 4) * 8;
                uint32_t ah[2][4], al[2][4];
                #pragma unroll
                for (int mi = 0; mi < 2; mi++) {
                    int row = wm * 32 + mi * 16 + (lane & 15);
                    ldmx4(ah[mi], &Ahi[row * ATP + acol]);
                    ldmx4(al[mi], &Alo[row * ATP + acol]);
                }
                uint32_t bh[2][4], bl[2][4];
                #pragma unroll
                for (int pr = 0; pr < 2; pr++) {
                    int row = wn * 32 + pr * 16 + (lane & 15);
                    ldmx4(bh[pr], &Bhi[row * ATP + acol]);
                    ldmx4(bl[pr], &Blo[row * ATP + acol]);
                }
                #pragma unroll
                for (int mi = 0; mi < 2; mi++)
                    #pragma unroll
                    for (int ni = 0; ni < 4; ni++) {
                        uint32_t bb[2];
                        // hi * hi
                        bb[0] = bh[ni >> 1][ni & 1];
                        bb[1] = bh[ni >> 1][(ni & 1) + 2];
                        mma16816(acc[mi][ni], ah[mi], bb);
                        // lo * hi
                        mma16816(acc[mi][ni], al[mi], bb);
                        // hi * lo
                        bb[0] = bl[ni >> 1][ni & 1];
                        bb[1] = bl[ni >> 1][(ni & 1) + 2];
                        mma16816(acc[mi][ni], ah[mi], bb);
                    }
            }
            __syncthreads();
        }

        // epilogue A: bias + relu + split -> Hs [hi(64)|lo(64)] stride HSTR
        #pragma unroll
        for (int mi = 0; mi < 2; mi++)
            #pragma unroll
            for (int ni = 0; ni < 4; ni++) {
                int row0 = wm * 32 + mi * 16 + (lane >> 2);
                int col0 = wn * 32 + ni * 8 + 2 * (lane & 3);
                int gc = nt * 64 + col0;
                float bv0 = b1[gc];
                float bv1 = b1[gc + 1];
                #pragma unroll
                for (int half = 0; half < 2; half++) {
                    int row = row0 + half * 8;
                    float a0 = acc[mi][ni][half * 2 + 0] + bv0;
                    float a1 = acc[mi][ni][half * 2 + 1] + bv1;
                    a0 = fmaxf(a0, 0.0f);
                    a1 = fmaxf(a1, 0.0f);
                    __nv_bfloat16 h0 = __float2bfloat16(a0);
                    __nv_bfloat16 h1 = __float2bfloat16(a1);
                    __nv_bfloat162 hip; hip.x = h0; hip.y = h1;
                    __nv_bfloat162 lop;
                    lop.x = __float2bfloat16(a0 - __bfloat162float(h0));
                    lop.y = __float2bfloat16(a1 - __bfloat162float(h1));
                    *(__nv_bfloat162*)&Hs[row * HSTR + col0]      = hip;
                    *(__nv_bfloat162*)&Hs[row * HSTR + 64 + col0] = lop;
                }
            }

        // stage Wf chunk: 64 rows x [hi64|lo64] -> Wfs stride HSTR
        for (int idx = tid; idx < 64 * 16; idx += 256) {
            int r = idx >> 4;
            int sub = idx & 15;
            int part = sub >> 3;            // 0=hi, 1=lo
            int q = sub & 7;
            uint4 v = *(const uint4*)&Wf16[(size_t)r * (2 * HH) + part * HH + nt * 64 + q * 8];
            *(uint4*)&Wfs[r * HSTR + part * 64 + q * 8] = v;
        }
        __syncthreads();

        // ---------------- phase B: p += Hs' (K=64, logical 192) x Wfs'^T ---
        for (int k0 = 0; k0 < 3 * 64; k0 += 16) {
            int seg = k0 >> 6;
            int kk = k0 & 63;
            int aoff = (seg == 2 ? 64 : 0) + kk;
            int boff = (seg == 1 ? 64 : 0) + kk;

            uint32_t afr[2][4];
            #pragma unroll
            for (int mi = 0; mi < 2; mi++) {
                int row = wm * 32 + mi * 16 + (lane & 15);
                ldmx4(afr[mi], &Hs[row * HSTR + aoff + (lane >> 4) * 8]);
            }
            uint32_t bfr[2][4];
            #pragma unroll
            for (int pr = 0; pr < 2; pr++) {
                int row = wn * 32 + pr * 16 + (lane & 15);
                ldmx4(bfr[pr], &Wfs[row * HSTR + boff + (lane >> 4) * 8]);
            }
            #pragma unroll
            for (int mi = 0; mi < 2; mi++)
                #pragma unroll
                for (int ni = 0; ni < 4; ni++) {
                    uint32_t bb[2];
                    bb[0] = bfr[ni >> 1][ni & 1];
                    bb[1] = bfr[ni >> 1][(ni & 1) + 2];
                    mma16816(acc2[mi][ni], afr[mi], bb);
                }
        }
        __syncthreads();   // protect Hs/Wfs before next nt overwrites
    }

    // epilogue: write p (stride PSTR, cols < CC, rows < M)
    #pragma unroll
    for (int mi = 0; mi < 2; mi++)
        #pragma unroll
        for (int ni = 0; ni < 4; ni++) {
            int col0 = wn * 32 + ni * 8 + 2 * (lane & 3);
            if (col0 >= CC) continue;
            int row0 = bm + wm * 32 + mi * 16 + (lane >> 2);
            if (row0 < M)
                *(float2*)&P[(size_t)row0 * PSTR + col0] =
                    make_float2(acc2[mi][ni][0], acc2[mi][ni][1]);
            if (row0 + 8 < M)
                *(float2*)&P[(size_t)(row0 + 8) * PSTR + col0] =
                    make_float2(acc2[mi][ni][2], acc2[mi][ni][3]);
        }
}

// ---------------- final aggregation at C=40: warp per node ------------------
__global__ __launch_bounds__(256)
void aggregate_final_kernel(float* __restrict__ out) {
    int node = blockIdx.x * 8 + (threadIdx.x >> 5);
    int lane = threadIdx.x & 31;
    if (node >= NN) return;

    const float* __restrict__ p = g_p;
    int start = g_rowptr[node];
    int d = g_deg[node];
    float di = g_dinv[node];

    float acc0 = 0.0f, acc1 = 0.0f;
    #pragma unroll 4
    for (int j = 0; j < d; j++) {
        int2 e = g_epack[start + j];      // uniform across warp -> broadcast
        float w = __int_as_float(e.y);
        const float* row = &p[(size_t)e.x * PSTR];
        acc0 += w * row[lane];
        if (lane < CC - 32) acc1 += w * row[32 + lane];
    }

    const float* self = &p[(size_t)node * PSTR];
    float v0 = di * acc0 + di * di * self[lane] + g_biasf[lane];
    out[(size_t)node * CC + lane] = v0;
    if (lane < CC - 32) {
        float v1 = di * acc1 + di * di * self[32 + lane] + g_biasf[32 + lane];
        out[(size_t)node * CC + 32 + lane] = v1;
    }
}

// ---------------- launch ----------------------------------------------------
extern "C" void kernel_launch(void* const* d_in, const int* in_sizes, int n_in,
                              void* d_out, int out_size) {
    const float* x    = (const float*)d_in[0];
    const int*   ei   = (const int*)d_in[1];
    const float* W1   = (const float*)d_in[2];
    const float* b1   = (const float*)d_in[3];
    const float* W2   = (const float*)d_in[4];
    const float* b2   = (const float*)d_in[5];
    const float* Wout = (const float*)d_in[6];
    const float* bout = (const float*)d_in[7];
    float* out = (float*)d_out;

    const int* src = ei;         // edge_index[0]
    const int* dst = ei + EE;    // edge_index[1]

    __nv_bfloat16* a16;  cudaGetSymbolAddress((void**)&a16, g_a16);
    __nv_bfloat16* w16;  cudaGetSymbolAddress((void**)&w16, g_w16);
    __nv_bfloat16* wf16; cudaGetSymbolAddress((void**)&wf16, g_wf16);
    float* pbuf; cudaGetSymbolAddress((void**)&pbuf, g_p);

    cudaFuncSetAttribute(b2b_kernel, cudaFuncAttributeMaxDynamicSharedMemorySize,
                         41472 * (int)sizeof(__nv_bfloat16));

    // ---- prep: weights + zero deg (one kernel) ----
    prep_kernel<<<365, 256>>>(W1, W2, Wout, b2, bout);

    // ---- CSR build ----
    count_deg_kernel<<<(EE + 255) / 256, 256>>>(dst);
    scan_blocks_kernel<<<NB, 1024>>>();          // also computes dinv
    add_offsets_kernel<<<(NN + 255) / 256, 256>>>();   // inline partials prefix
    fill_csr_kernel<<<(EE + 255) / 256, 256>>>(src, dst);

    // ---- agg(x) -> split a16 ----
    aggregate_split_kernel<<<NN, FF>>>(x);

    // ---- fused B2B: p = relu(a16 @ W1'^T + b1) @ Wf'^T ----
    b2b_kernel<<<(NN + 127) / 128, 256, 41472 * sizeof(__nv_bfloat16)>>>(
        a16, w16, wf16, b1, pbuf, NN);

    // ---- final aggregation at C=40 -> out ----
    aggregate_final_kernel<<<(NN + 7) / 8, 256>>>(out);
}

// round 14
// speedup vs baseline: 1.3055x; 1.0829x over previous
#include <cuda_runtime.h>
#include <cuda_bf16.h>
#include <cstdint>

#define NN 50000
#define EE 800000
#define FF 128
#define HH 256
#define CC 40
#define PSTR 64                   // padded p row stride
#define NB ((NN + 1023) / 1024)   // 49 scan blocks

// ---------------- scratch (device globals; no runtime allocation) ----------
__device__ __nv_bfloat16 g_a16[(size_t)NN * 2 * FF];   // split agg(x)  [N,256]=[hi|lo]
__device__ __nv_bfloat16 g_w16[(size_t)HH * 2 * FF];   // split W1 [256][hi128|lo128]
__device__ __nv_bfloat16 g_wf16[(size_t)64 * 2 * HH];  // split Wf [64][hi256|lo256]
__device__ float g_p[(size_t)NN * PSTR];               // pre-agg logits [N,40] pad 64
__device__ float g_biasf[CC];                          // fused bias
__device__ int   g_deg[NN];
__device__ float g_dinv[NN];
__device__ int   g_rowptr[NN];
__device__ int   g_cursor[NN];
__device__ int   g_partials[64];
__device__ int2  g_epack[EE];                          // {src, dinv[src] bits}

// ---------------- combined prep ---------------------------------------------
__global__ void prep_kernel(const float* __restrict__ W1, const float* __restrict__ W2,
                            const float* __restrict__ Wout, const float* __restrict__ b2,
                            const float* __restrict__ bout) {
    __shared__ float sh[256];
    int b = blockIdx.x;
    int t = threadIdx.x;
    if (b < 128) {
        int idx = b * 256 + t;
        int n = idx >> 7;            // row 0..255
        int k = idx & 127;
        float v = W1[(size_t)n * FF + k];
        __nv_bfloat16 hi = __float2bfloat16(v);
        __nv_bfloat16 lo = __float2bfloat16(v - __bfloat162float(hi));
        g_w16[(size_t)n * (2 * FF) + k]      = hi;
        g_w16[(size_t)n * (2 * FF) + FF + k] = lo;
    } else if (b < 168) {
        int c = b - 128;             // 0..39
        float wc = Wout[(size_t)c * HH + t];
        float acc = 0.0f;
        #pragma unroll 4
        for (int o = 0; o < HH; o++)
            acc += Wout[(size_t)c * HH + o] * W2[(size_t)o * HH + t];
        __nv_bfloat16 hi = __float2bfloat16(acc);
        __nv_bfloat16 lo = __float2bfloat16(acc - __bfloat162float(hi));
        g_wf16[(size_t)c * (2 * HH) + t]      = hi;
        g_wf16[(size_t)c * (2 * HH) + HH + t] = lo;
        sh[t] = wc * b2[t];
        __syncthreads();
        for (int off = 128; off > 0; off >>= 1) {
            if (t < off) sh[t] += sh[t + off];
            __syncthreads();
        }
        if (t == 0) g_biasf[c] = bout[c] + sh[0];
    } else if (b == 168) {
        __nv_bfloat16 z = __float2bfloat16(0.0f);
        for (int idx = t; idx < 24 * 2 * HH; idx += 256)
            g_wf16[(size_t)40 * (2 * HH) + idx] = z;
    } else {
        int i = (b - 169) * 256 + t;
        if (i < NN) g_deg[i] = 0;
    }
}

// ---------------- CSR build ------------------------------------------------
__global__ void count_deg_kernel(const int* __restrict__ dst) {
    int e = blockIdx.x * blockDim.x + threadIdx.x;
    if (e < EE) atomicAdd(&g_deg[dst[e]], 1);
}

__global__ void scan_blocks_kernel() {
    __shared__ int sh[1024];
    int t = threadIdx.x;
    int i = blockIdx.x * 1024 + t;
    int v = (i < NN) ? g_deg[i] : 0;
    if (i < NN) g_dinv[i] = rsqrtf((float)v + 1.0f);   // fused dinv
    sh[t] = v;
    __syncthreads();
    #pragma unroll
    for (int off = 1; off < 1024; off <<= 1) {
        int add = (t >= off) ? sh[t - off] : 0;
        __syncthreads();
        sh[t] += add;
        __syncthreads();
    }
    if (i < NN) g_rowptr[i] = sh[t] - v;   // exclusive prefix within block
    if (t == 1023) g_partials[blockIdx.x] = sh[1023];   // raw block sums
}

// add block-prefix of partials inline (warp-reduce over <=49 raw sums)
__global__ void add_offsets_kernel() {
    __shared__ int s_pref;
    int i = blockIdx.x * blockDim.x + threadIdx.x;
    int grp = (blockIdx.x * 256) >> 10;   // constant per 256-thread block
    if (threadIdx.x < 32) {
        int acc = 0;
        for (int b = threadIdx.x; b < grp; b += 32) acc += g_partials[b];
        #pragma unroll
        for (int off = 16; off; off >>= 1) acc += __shfl_xor_sync(~0u, acc, off);
        if (threadIdx.x == 0) s_pref = acc;
    }
    __syncthreads();
    if (i < NN) {
        int v = g_rowptr[i] + s_pref;
        g_rowptr[i] = v;
        g_cursor[i] = v;
    }
}

// 4 edges per thread, phase-batched for atomic MLP
__global__ void fill_csr_kernel(const int* __restrict__ src, const int* __restrict__ dst) {
    int e0 = (blockIdx.x * blockDim.x + threadIdx.x) * 4;
    int s[4], dd[4];
    float w[4];
    int cnt = EE - e0;
    if (cnt <= 0) return;
    if (cnt > 4) cnt = 4;
    #pragma unroll
    for (int k = 0; k < 4; k++) {
        if (k < cnt) {
            s[k] = src[e0 + k];
            dd[k] = dst[e0 + k];
        }
    }
    #pragma unroll
    for (int k = 0; k < 4; k++)
        if (k < cnt) w[k] = g_dinv[s[k]];
    int pos[4];
    #pragma unroll
    for (int k = 0; k < 4; k++)
        if (k < cnt) pos[k] = atomicAdd(&g_cursor[dd[k]], 1);
    #pragma unroll
    for (int k = 0; k < 4; k++)
        if (k < cnt) g_epack[pos[k]] = make_int2(s[k], __float_as_int(w[k]));
}

// ---------------- agg(x): 64 threads/node, float2 channels -------------------
__global__ __launch_bounds__(64)
void aggregate_split_kernel(const float* __restrict__ h) {
    int i = blockIdx.x;
    int c = threadIdx.x;          // 0..63 -> channels 2c, 2c+1
    __shared__ int2 s_e[64];

    int start = g_rowptr[i];
    int d = g_deg[i];
    float di = g_dinv[i];
    float ax = 0.0f, ay = 0.0f;

    for (int base = 0; base < d; base += 64) {
        int n = d - base;
        if (n > 64) n = 64;
        __syncthreads();
        if (c < n) s_e[c] = g_epack[start + base + c];
        __syncthreads();
        #pragma unroll 4
        for (int j = 0; j < n; j++) {
            int2 e = s_e[j];
            float w = __int_as_float(e.y);
            float2 v = *(const float2*)&h[(size_t)e.x * FF + 2 * c];
            ax += w * v.x;
            ay += w * v.y;
        }
    }

    float2 self = *(const float2*)&h[(size_t)i * FF + 2 * c];
    float v0 = di * ax + di * di * self.x;
    float v1 = di * ay + di * di * self.y;
    __nv_bfloat16 h0 = __float2bfloat16(v0);
    __nv_bfloat16 h1 = __float2bfloat16(v1);
    __nv_bfloat162 hip; hip.x = h0; hip.y = h1;
    __nv_bfloat162 lop;
    lop.x = __float2bfloat16(v0 - __bfloat162float(h0));
    lop.y = __float2bfloat16(v1 - __bfloat162float(h1));
    size_t b = (size_t)i * (2 * FF);
    *(__nv_bfloat162*)&g_a16[b + 2 * c]      = hip;
    *(__nv_bfloat162*)&g_a16[b + FF + 2 * c] = lop;
}

// ---------------- mma helpers -----------------------------------------------
__device__ __forceinline__ void ldmx4(uint32_t* r, const __nv_bfloat16* p) {
    uint32_t addr = (uint32_t)__cvta_generic_to_shared(p);
    asm volatile("ldmatrix.sync.aligned.m8n8.x4.shared.b16 {%0,%1,%2,%3}, [%4];"
                 : "=r"(r[0]), "=r"(r[1]), "=r"(r[2]), "=r"(r[3]) : "r"(addr));
}

__device__ __forceinline__ void mma16816(float* d, const uint32_t* a, const uint32_t* b) {
    asm volatile(
        "mma.sync.aligned.m16n8k16.row.col.f32.bf16.bf16.f32 "
        "{%0,%1,%2,%3}, {%4,%5,%6,%7}, {%8,%9}, {%0,%1,%2,%3};"
        : "+f"(d[0]), "+f"(d[1]), "+f"(d[2]), "+f"(d[3])
        : "r"(a[0]), "r"(a[1]), "r"(a[2]), "r"(a[3]), "r"(b[0]), "r"(b[1]));
}

// ---------------- B2B kernel: p = relu(a16*W1'^T+b1) * Wf'^T ----------------
#define HSTR 136
#define ATP 40

__global__ __launch_bounds__(256, 2)
void b2b_kernel(const __nv_bfloat16* __restrict__ A,
                const __nv_bfloat16* __restrict__ W1s,
                const __nv_bfloat16* __restrict__ Wf16,
                const float* __restrict__ b1,
                float* __restrict__ P, int M) {
    extern __shared__ __nv_bfloat16 smem[];
    __nv_bfloat16* Ahi = smem;                 // 128*40 = 5120
    __nv_bfloat16* Alo = smem + 5120;          // 5120
    __nv_bfloat16* Bhi = smem + 10240;         // 64*40 = 2560
    __nv_bfloat16* Blo = smem + 12800;         // 2560
    __nv_bfloat16* Hs  = smem + 15360;         // 128*136 = 17408
    __nv_bfloat16* Wfs = smem + 32768;         // 64*136 = 8704  (total 41472)

    int tid = threadIdx.x;
    int bm = blockIdx.x * 128;
    int wid = tid >> 5;
    int lane = tid & 31;
    int wm = wid >> 1;          // 0..3 : 32-row slab
    int wn = wid & 1;           // 0..1 : 32-col slab

    float acc2[2][4][4];
    #pragma unroll
    for (int i = 0; i < 2; i++)
        #pragma unroll
        for (int j = 0; j < 4; j++)
            #pragma unroll
            for (int v = 0; v < 4; v++) acc2[i][j][v] = 0.0f;

    for (int nt = 0; nt < 4; nt++) {
        // ---------------- phase A ----------------
        float acc[2][4][4];
        #pragma unroll
        for (int i = 0; i < 2; i++)
            #pragma unroll
            for (int j = 0; j < 4; j++)
                #pragma unroll
                for (int v = 0; v < 4; v++) acc[i][j][v] = 0.0f;

        for (int kk = 0; kk < FF; kk += 32) {
            // stage A hi+lo: 128 rows x 32 halves each
            #pragma unroll
            for (int it = 0; it < 2; it++) {
                int idx = tid + it * 256;
                int r = idx >> 2;
                int q = idx & 3;
                int m = bm + r;
                uint4 vh = make_uint4(0u, 0u, 0u, 0u);
                uint4 vl = make_uint4(0u, 0u, 0u, 0u);
                if (m < M) {
                    const __nv_bfloat16* base = &A[(size_t)m * (2 * FF) + kk + q * 8];
                    vh = *(const uint4*)base;
                    vl = *(const uint4*)(base + FF);
                }
                *(uint4*)&Ahi[r * ATP + q * 8] = vh;
                *(uint4*)&Alo[r * ATP + q * 8] = vl;
            }
            // stage W1 hi+lo: 64 rows x 32 halves each
            {
                int r = tid >> 2;
                int q = tid & 3;
                const __nv_bfloat16* base =
                    &W1s[(size_t)(nt * 64 + r) * (2 * FF) + kk + q * 8];
                *(uint4*)&Bhi[r * ATP + q * 8] = *(const uint4*)base;
                *(uint4*)&Blo[r * ATP + q * 8] = *(const uint4*)(base + FF);
            }
            __syncthreads();

            #pragma unroll
            for (int ks = 0; ks < 2; ks++) {
                int acol = ks * 16 + (lane >> 4) * 8;
                uint32_t ah[2][4], al[2][4];
                #pragma unroll
                for (int mi = 0; mi < 2; mi++) {
                    int row = wm * 32 + mi * 16 + (lane & 15);
                    ldmx4(ah[mi], &Ahi[row * ATP + acol]);
                    ldmx4(al[mi], &Alo[row * ATP + acol]);
                }
                uint32_t bh[2][4], bl[2][4];
                #pragma unroll
                for (int pr = 0; pr < 2; pr++) {
                    int row = wn * 32 + pr * 16 + (lane & 15);
                    ldmx4(bh[pr], &Bhi[row * ATP + acol]);
                    ldmx4(bl[pr], &Blo[row * ATP + acol]);
                }
                #pragma unroll
                for (int mi = 0; mi < 2; mi++)
                    #pragma unroll
                    for (int ni = 0; ni < 4; ni++) {
                        uint32_t bb[2];
                        // hi * hi
                        bb[0] = bh[ni >> 1][ni & 1];
                        bb[1] = bh[ni >> 1][(ni & 1) + 2];
                        mma16816(acc[mi][ni], ah[mi], bb);
                        // lo * hi
                        mma16816(acc[mi][ni], al[mi], bb);
                        // hi * lo
                        bb[0] = bl[ni >> 1][ni & 1];
                        bb[1] = bl[ni >> 1][(ni & 1) + 2];
                        mma16816(acc[mi][ni], ah[mi], bb);
                    }
            }
            __syncthreads();
        }

        // epilogue A: bias + relu + split -> Hs [hi(64)|lo(64)] stride HSTR
        #pragma unroll
        for (int mi = 0; mi < 2; mi++)
            #pragma unroll
            for (int ni = 0; ni < 4; ni++) {
                int row0 = wm * 32 + mi * 16 + (lane >> 2);
                int col0 = wn * 32 + ni * 8 + 2 * (lane & 3);
                int gc = nt * 64 + col0;
                float bv0 = b1[gc];
                float bv1 = b1[gc + 1];
                #pragma unroll
                for (int half = 0; half < 2; half++) {
                    int row = row0 + half * 8;
                    float a0 = acc[mi][ni][half * 2 + 0] + bv0;
                    float a1 = acc[mi][ni][half * 2 + 1] + bv1;
                    a0 = fmaxf(a0, 0.0f);
                    a1 = fmaxf(a1, 0.0f);
                    __nv_bfloat16 h0 = __float2bfloat16(a0);
                    __nv_bfloat16 h1 = __float2bfloat16(a1);
                    __nv_bfloat162 hip; hip.x = h0; hip.y = h1;
                    __nv_bfloat162 lop;
                    lop.x = __float2bfloat16(a0 - __bfloat162float(h0));
                    lop.y = __float2bfloat16(a1 - __bfloat162float(h1));
                    *(__nv_bfloat162*)&Hs[row * HSTR + col0]      = hip;
                    *(__nv_bfloat162*)&Hs[row * HSTR + 64 + col0] = lop;
                }
            }

        // stage Wf chunk: 64 rows x [hi64|lo64] -> Wfs stride HSTR
        for (int idx = tid; idx < 64 * 16; idx += 256) {
            int r = idx >> 4;
            int sub = idx & 15;
            int part = sub >> 3;            // 0=hi, 1=lo
            int q = sub & 7;
            uint4 v = *(const uint4*)&Wf16[(size_t)r * (2 * HH) + part * HH + nt * 64 + q * 8];
            *(uint4*)&Wfs[r * HSTR + part * 64 + q * 8] = v;
        }
        __syncthreads();

        // ---------------- phase B: p += Hs' (K=64, logical 192) x Wfs'^T ---
        for (int k0 = 0; k0 < 3 * 64; k0 += 16) {
            int seg = k0 >> 6;
            int kk = k0 & 63;
            int aoff = (seg == 2 ? 64 : 0) + kk;
            int boff = (seg == 1 ? 64 : 0) + kk;

            uint32_t afr[2][4];
            #pragma unroll
            for (int mi = 0; mi < 2; mi++) {
                int row = wm * 32 + mi * 16 + (lane & 15);
                ldmx4(afr[mi], &Hs[row * HSTR + aoff + (lane >> 4) * 8]);
            }
            uint32_t bfr[2][4];
            #pragma unroll
            for (int pr = 0; pr < 2; pr++) {
                int row = wn * 32 + pr * 16 + (lane & 15);
                ldmx4(bfr[pr], &Wfs[row * HSTR + boff + (lane >> 4) * 8]);
            }
            #pragma unroll
            for (int mi = 0; mi < 2; mi++)
                #pragma unroll
                for (int ni = 0; ni < 4; ni++) {
                    uint32_t bb[2];
                    bb[0] = bfr[ni >> 1][ni & 1];
                    bb[1] = bfr[ni >> 1][(ni & 1) + 2];
                    mma16816(acc2[mi][ni], afr[mi], bb);
                }
        }
        __syncthreads();   // protect Hs/Wfs before next nt overwrites
    }

    // epilogue: write p (stride PSTR, cols < CC, rows < M)
    #pragma unroll
    for (int mi = 0; mi < 2; mi++)
        #pragma unroll
        for (int ni = 0; ni < 4; ni++) {
            int col0 = wn * 32 + ni * 8 + 2 * (lane & 3);
            if (col0 >= CC) continue;
            int row0 = bm + wm * 32 + mi * 16 + (lane >> 2);
            if (row0 < M)
                *(float2*)&P[(size_t)row0 * PSTR + col0] =
                    make_float2(acc2[mi][ni][0], acc2[mi][ni][1]);
            if (row0 + 8 < M)
                *(float2*)&P[(size_t)(row0 + 8) * PSTR + col0] =
                    make_float2(acc2[mi][ni][2], acc2[mi][ni][3]);
        }
}

// ---------------- final aggregation at C=40: warp per node ------------------
__global__ __launch_bounds__(256)
void aggregate_final_kernel(float* __restrict__ out) {
    int node = blockIdx.x * 8 + (threadIdx.x >> 5);
    int lane = threadIdx.x & 31;
    if (node >= NN) return;

    const float* __restrict__ p = g_p;
    int start = g_rowptr[node];
    int d = g_deg[node];
    float di = g_dinv[node];

    float acc0 = 0.0f, acc1 = 0.0f;
    #pragma unroll 4
    for (int j = 0; j < d; j++) {
        int2 e = g_epack[start + j];      // uniform across warp -> broadcast
        float w = __int_as_float(e.y);
        const float* row = &p[(size_t)e.x * PSTR];
        acc0 += w * row[lane];
        if (lane < CC - 32) acc1 += w * row[32 + lane];
    }

    const float* self = &p[(size_t)node * PSTR];
    float v0 = di * acc0 + di * di * self[lane] + g_biasf[lane];
    out[(size_t)node * CC + lane] = v0;
    if (lane < CC - 32) {
        float v1 = di * acc1 + di * di * self[32 + lane] + g_biasf[32 + lane];
        out[(size_t)node * CC + 32 + lane] = v1;
    }
}

// ---------------- launch ----------------------------------------------------
extern "C" void kernel_launch(void* const* d_in, const int* in_sizes, int n_in,
                              void* d_out, int out_size) {
    const float* x    = (const float*)d_in[0];
    const int*   ei   = (const int*)d_in[1];
    const float* W1   = (const float*)d_in[2];
    const float* b1   = (const float*)d_in[3];
    const float* W2   = (const float*)d_in[4];
    const float* b2   = (const float*)d_in[5];
    const float* Wout = (const float*)d_in[6];
    const float* bout = (const float*)d_in[7];
    float* out = (float*)d_out;

    const int* src = ei;         // edge_index[0]
    const int* dst = ei + EE;    // edge_index[1]

    __nv_bfloat16* a16;  cudaGetSymbolAddress((void**)&a16, g_a16);
    __nv_bfloat16* w16;  cudaGetSymbolAddress((void**)&w16, g_w16);
    __nv_bfloat16* wf16; cudaGetSymbolAddress((void**)&wf16, g_wf16);
    float* pbuf; cudaGetSymbolAddress((void**)&pbuf, g_p);

    cudaFuncSetAttribute(b2b_kernel, cudaFuncAttributeMaxDynamicSharedMemorySize,
                         41472 * (int)sizeof(__nv_bfloat16));

    // ---- prep: weights + zero deg (one kernel) ----
    prep_kernel<<<365, 256>>>(W1, W2, Wout, b2, bout);

    // ---- CSR build ----
    count_deg_kernel<<<(EE + 255) / 256, 256>>>(dst);
    scan_blocks_kernel<<<NB, 1024>>>();          // also computes dinv
    add_offsets_kernel<<<(NN + 255) / 256, 256>>>();   // inline partials prefix
    fill_csr_kernel<<<(EE / 4 + 255) / 256, 256>>>(src, dst);

    // ---- agg(x) -> split a16 (64 threads/node, float2) ----
    aggregate_split_kernel<<<NN, 64>>>(x);

    // ---- fused B2B: p = relu(a16 @ W1'^T + b1) @ Wf'^T ----
    b2b_kernel<<<(NN + 127) / 128, 256, 41472 * sizeof(__nv_bfloat16)>>>(
        a16, w16, wf16, b1, pbuf, NN);

    // ---- final aggregation at C=40 -> out ----
    aggregate_final_kernel<<<(NN + 7) / 8, 256>>>(out);
}

// round 15
// speedup vs baseline: 1.3153x; 1.0075x over previous
#include <cuda_runtime.h>
#include <cuda_bf16.h>
#include <cstdint>

#define NN 50000
#define EE 800000
#define FF 128
#define HH 256
#define CC 40
#define PSTR 64                   // padded p row stride
#define NB ((NN + 1023) / 1024)   // 49 scan blocks

// ---------------- scratch (device globals; no runtime allocation) ----------
__device__ __nv_bfloat16 g_a16[(size_t)NN * 2 * FF];   // split agg(x)  [N,256]=[hi|lo]
__device__ __nv_bfloat16 g_w16[(size_t)HH * 2 * FF];   // split W1 [256][hi128|lo128]
__device__ __nv_bfloat16 g_wf16[(size_t)64 * 2 * HH];  // split Wf [64][hi256|lo256]
__device__ float g_p[(size_t)NN * PSTR];               // pre-agg logits [N,40] pad 64
__device__ float g_biasf[CC];                          // fused bias
__device__ int   g_deg[NN];
__device__ float g_dinv[NN];
__device__ int   g_rowptr[NN];
__device__ int   g_cursor[NN];
__device__ int   g_partials[64];
__device__ int2  g_epack[EE];                          // {src, dinv[src] bits}

// ---------------- combined prep ---------------------------------------------
__global__ void prep_kernel(const float* __restrict__ W1, const float* __restrict__ W2,
                            const float* __restrict__ Wout, const float* __restrict__ b2,
                            const float* __restrict__ bout) {
    __shared__ float sh[256];
    int b = blockIdx.x;
    int t = threadIdx.x;
    if (b < 128) {
        int idx = b * 256 + t;
        int n = idx >> 7;            // row 0..255
        int k = idx & 127;
        float v = W1[(size_t)n * FF + k];
        __nv_bfloat16 hi = __float2bfloat16(v);
        __nv_bfloat16 lo = __float2bfloat16(v - __bfloat162float(hi));
        g_w16[(size_t)n * (2 * FF) + k]      = hi;
        g_w16[(size_t)n * (2 * FF) + FF + k] = lo;
    } else if (b < 168) {
        int c = b - 128;             // 0..39
        float wc = Wout[(size_t)c * HH + t];
        float acc = 0.0f;
        #pragma unroll 4
        for (int o = 0; o < HH; o++)
            acc += Wout[(size_t)c * HH + o] * W2[(size_t)o * HH + t];
        __nv_bfloat16 hi = __float2bfloat16(acc);
        __nv_bfloat16 lo = __float2bfloat16(acc - __bfloat162float(hi));
        g_wf16[(size_t)c * (2 * HH) + t]      = hi;
        g_wf16[(size_t)c * (2 * HH) + HH + t] = lo;
        sh[t] = wc * b2[t];
        __syncthreads();
        for (int off = 128; off > 0; off >>= 1) {
            if (t < off) sh[t] += sh[t + off];
            __syncthreads();
        }
        if (t == 0) g_biasf[c] = bout[c] + sh[0];
    } else if (b == 168) {
        __nv_bfloat16 z = __float2bfloat16(0.0f);
        for (int idx = t; idx < 24 * 2 * HH; idx += 256)
            g_wf16[(size_t)40 * (2 * HH) + idx] = z;
    } else {
        int i = (b - 169) * 256 + t;
        if (i < NN) g_deg[i] = 0;
    }
}

// ---------------- CSR build ------------------------------------------------
// 4 edges per thread, phase-batched for atomic MLP
__global__ void count_deg_kernel(const int* __restrict__ dst) {
    int e0 = (blockIdx.x * blockDim.x + threadIdx.x) * 4;
    int cnt = EE - e0;
    if (cnt <= 0) return;
    if (cnt > 4) cnt = 4;
    int dd[4];
    #pragma unroll
    for (int k = 0; k < 4; k++)
        if (k < cnt) dd[k] = dst[e0 + k];
    #pragma unroll
    for (int k = 0; k < 4; k++)
        if (k < cnt) atomicAdd(&g_deg[dd[k]], 1);
}

__global__ void scan_blocks_kernel() {
    __shared__ int sh[1024];
    int t = threadIdx.x;
    int i = blockIdx.x * 1024 + t;
    int v = (i < NN) ? g_deg[i] : 0;
    if (i < NN) g_dinv[i] = rsqrtf((float)v + 1.0f);   // fused dinv
    sh[t] = v;
    __syncthreads();
    #pragma unroll
    for (int off = 1; off < 1024; off <<= 1) {
        int add = (t >= off) ? sh[t - off] : 0;
        __syncthreads();
        sh[t] += add;
        __syncthreads();
    }
    if (i < NN) g_rowptr[i] = sh[t] - v;   // exclusive prefix within block
    if (t == 1023) g_partials[blockIdx.x] = sh[1023];   // raw block sums
}

// add block-prefix of partials inline (warp-reduce over <=49 raw sums)
__global__ void add_offsets_kernel() {
    __shared__ int s_pref;
    int i = blockIdx.x * blockDim.x + threadIdx.x;
    int grp = (blockIdx.x * 256) >> 10;   // constant per 256-thread block
    if (threadIdx.x < 32) {
        int acc = 0;
        for (int b = threadIdx.x; b < grp; b += 32) acc += g_partials[b];
        #pragma unroll
        for (int off = 16; off; off >>= 1) acc += __shfl_xor_sync(~0u, acc, off);
        if (threadIdx.x == 0) s_pref = acc;
    }
    __syncthreads();
    if (i < NN) {
        int v = g_rowptr[i] + s_pref;
        g_rowptr[i] = v;
        g_cursor[i] = v;
    }
}

// 4 edges per thread, phase-batched for atomic MLP
__global__ void fill_csr_kernel(const int* __restrict__ src, const int* __restrict__ dst) {
    int e0 = (blockIdx.x * blockDim.x + threadIdx.x) * 4;
    int s[4], dd[4];
    float w[4];
    int cnt = EE - e0;
    if (cnt <= 0) return;
    if (cnt > 4) cnt = 4;
    #pragma unroll
    for (int k = 0; k < 4; k++) {
        if (k < cnt) {
            s[k] = src[e0 + k];
            dd[k] = dst[e0 + k];
        }
    }
    #pragma unroll
    for (int k = 0; k < 4; k++)
        if (k < cnt) w[k] = g_dinv[s[k]];
    int pos[4];
    #pragma unroll
    for (int k = 0; k < 4; k++)
        if (k < cnt) pos[k] = atomicAdd(&g_cursor[dd[k]], 1);
    #pragma unroll
    for (int k = 0; k < 4; k++)
        if (k < cnt) g_epack[pos[k]] = make_int2(s[k], __float_as_int(w[k]));
}

// ---------------- agg(x): warp per node, float4, shuffle broadcast -----------
__global__ __launch_bounds__(256)
void aggregate_split_kernel(const float* __restrict__ h) {
    int node = blockIdx.x * 8 + (threadIdx.x >> 5);
    int lane = threadIdx.x & 31;
    if (node >= NN) return;

    int start = g_rowptr[node];
    int d = g_deg[node];
    float di = g_dinv[node];
    float ax = 0.0f, ay = 0.0f, az = 0.0f, aw = 0.0f;

    for (int base = 0; base < d; base += 32) {
        int n = d - base;
        if (n > 32) n = 32;
        int2 e = make_int2(0, 0);
        if (lane < n) e = g_epack[start + base + lane];
        #pragma unroll 4
        for (int j = 0; j < n; j++) {
            int sv = __shfl_sync(~0u, e.x, j);
            float w = __int_as_float(__shfl_sync(~0u, e.y, j));
            float4 v = *(const float4*)&h[(size_t)sv * FF + 4 * lane];
            ax += w * v.x;
            ay += w * v.y;
            az += w * v.z;
            aw += w * v.w;
        }
    }

    float4 self = *(const float4*)&h[(size_t)node * FF + 4 * lane];
    float dd = di * di;
    float v0 = di * ax + dd * self.x;
    float v1 = di * ay + dd * self.y;
    float v2 = di * az + dd * self.z;
    float v3 = di * aw + dd * self.w;

    __nv_bfloat162 h01, h23, l01, l23;
    h01.x = __float2bfloat16(v0);  h01.y = __float2bfloat16(v1);
    h23.x = __float2bfloat16(v2);  h23.y = __float2bfloat16(v3);
    l01.x = __float2bfloat16(v0 - __bfloat162float(h01.x));
    l01.y = __float2bfloat16(v1 - __bfloat162float(h01.y));
    l23.x = __float2bfloat16(v2 - __bfloat162float(h23.x));
    l23.y = __float2bfloat16(v3 - __bfloat162float(h23.y));

    size_t b = (size_t)node * (2 * FF) + 4 * lane;
    uint2 hp, lp;
    hp.x = *(uint32_t*)&h01;  hp.y = *(uint32_t*)&h23;
    lp.x = *(uint32_t*)&l01;  lp.y = *(uint32_t*)&l23;
    *(uint2*)&g_a16[b]      = hp;
    *(uint2*)&g_a16[b + FF] = lp;
}

// ---------------- mma helpers -----------------------------------------------
__device__ __forceinline__ void ldmx4(uint32_t* r, const __nv_bfloat16* p) {
    uint32_t addr = (uint32_t)__cvta_generic_to_shared(p);
    asm volatile("ldmatrix.sync.aligned.m8n8.x4.shared.b16 {%0,%1,%2,%3}, [%4];"
                 : "=r"(r[0]), "=r"(r[1]), "=r"(r[2]), "=r"(r[3]) : "r"(addr));
}

__device__ __forceinline__ void mma16816(float* d, const uint32_t* a, const uint32_t* b) {
    asm volatile(
        "mma.sync.aligned.m16n8k16.row.col.f32.bf16.bf16.f32 "
        "{%0,%1,%2,%3}, {%4,%5,%6,%7}, {%8,%9}, {%0,%1,%2,%3};"
        : "+f"(d[0]), "+f"(d[1]), "+f"(d[2]), "+f"(d[3])
        : "r"(a[0]), "r"(a[1]), "r"(a[2]), "r"(a[3]), "r"(b[0]), "r"(b[1]));
}

// ---------------- B2B kernel: p = relu(a16*W1'^T+b1) * Wf'^T ----------------
#define HSTR 136
#define ATP 40

__global__ __launch_bounds__(256, 2)
void b2b_kernel(const __nv_bfloat16* __restrict__ A,
                const __nv_bfloat16* __restrict__ W1s,
                const __nv_bfloat16* __restrict__ Wf16,
                const float* __restrict__ b1,
                float* __restrict__ P, int M) {
    extern __shared__ __nv_bfloat16 smem[];
    __nv_bfloat16* Ahi = smem;                 // 128*40 = 5120
    __nv_bfloat16* Alo = smem + 5120;          // 5120
    __nv_bfloat16* Bhi = smem + 10240;         // 64*40 = 2560
    __nv_bfloat16* Blo = smem + 12800;         // 2560
    __nv_bfloat16* Hs  = smem + 15360;         // 128*136 = 17408
    __nv_bfloat16* Wfs = smem + 32768;         // 64*136 = 8704  (total 41472)

    int tid = threadIdx.x;
    int bm = blockIdx.x * 128;
    int wid = tid >> 5;
    int lane = tid & 31;
    int wm = wid >> 1;          // 0..3 : 32-row slab
    int wn = wid & 1;           // 0..1 : 32-col slab

    float acc2[2][4][4];
    #pragma unroll
    for (int i = 0; i < 2; i++)
        #pragma unroll
        for (int j = 0; j < 4; j++)
            #pragma unroll
            for (int v = 0; v < 4; v++) acc2[i][j][v] = 0.0f;

    for (int nt = 0; nt < 4; nt++) {
        // ---------------- phase A ----------------
        float acc[2][4][4];
        #pragma unroll
        for (int i = 0; i < 2; i++)
            #pragma unroll
            for (int j = 0; j < 4; j++)
                #pragma unroll
                for (int v = 0; v < 4; v++) acc[i][j][v] = 0.0f;

        for (int kk = 0; kk < FF; kk += 32) {
            // stage A hi+lo: 128 rows x 32 halves each
            #pragma unroll
            for (int it = 0; it < 2; it++) {
                int idx = tid + it * 256;
                int r = idx >> 2;
                int q = idx & 3;
                int m = bm + r;
                uint4 vh = make_uint4(0u, 0u, 0u, 0u);
                uint4 vl = make_uint4(0u, 0u, 0u, 0u);
                if (m < M) {
                    const __nv_bfloat16* base = &A[(size_t)m * (2 * FF) + kk + q * 8];
                    vh = *(const uint4*)base;
                    vl = *(const uint4*)(base + FF);
                }
                *(uint4*)&Ahi[r * ATP + q * 8] = vh;
                *(uint4*)&Alo[r * ATP + q * 8] = vl;
            }
            // stage W1 hi+lo: 64 rows x 32 halves each
            {
                int r = tid >> 2;
                int q = tid & 3;
                const __nv_bfloat16* base =
                    &W1s[(size_t)(nt * 64 + r) * (2 * FF) + kk + q * 8];
                *(uint4*)&Bhi[r * ATP + q * 8] = *(const uint4*)base;
                *(uint4*)&Blo[r * ATP + q * 8] = *(const uint4*)(base + FF);
            }
            __syncthreads();

            #pragma unroll
            for (int ks = 0; ks < 2; ks++) {
                int acol = ks * 16 + (lane >> 4) * 8;
                uint32_t ah[2][4], al[2][4];
                #pragma unroll
                for (int mi = 0; mi < 2; mi++) {
                    int row = wm * 32 + mi * 16 + (lane & 15);
                    ldmx4(ah[mi], &Ahi[row * ATP + acol]);
                    ldmx4(al[mi], &Alo[row * ATP + acol]);
                }
                uint32_t bh[2][4], bl[2][4];
                #pragma unroll
                for (int pr = 0; pr < 2; pr++) {
                    int row = wn * 32 + pr * 16 + (lane & 15);
                    ldmx4(bh[pr], &Bhi[row * ATP + acol]);
                    ldmx4(bl[pr], &Blo[row * ATP + acol]);
                }
                #pragma unroll
                for (int mi = 0; mi < 2; mi++)
                    #pragma unroll
                    for (int ni = 0; ni < 4; ni++) {
                        uint32_t bb[2];
                        // hi * hi
                        bb[0] = bh[ni >> 1][ni & 1];
                        bb[1] = bh[ni >> 1][(ni & 1) + 2];
                        mma16816(acc[mi][ni], ah[mi], bb);
                        // lo * hi
                        mma16816(acc[mi][ni], al[mi], bb);
                        // hi * lo
                        bb[0] = bl[ni >> 1][ni & 1];
                        bb[1] = bl[ni >> 1][(ni & 1) + 2];
                        mma16816(acc[mi][ni], ah[mi], bb);
                    }
            }
            __syncthreads();
        }

        // epilogue A: bias + relu + split -> Hs [hi(64)|lo(64)] stride HSTR
        #pragma unroll
        for (int mi = 0; mi < 2; mi++)
            #pragma unroll
            for (int ni = 0; ni < 4; ni++) {
                int row0 = wm * 32 + mi * 16 + (lane >> 2);
                int col0 = wn * 32 + ni * 8 + 2 * (lane & 3);
                int gc = nt * 64 + col0;
                float bv0 = b1[gc];
                float bv1 = b1[gc + 1];
                #pragma unroll
                for (int half = 0; half < 2; half++) {
                    int row = row0 + half * 8;
                    float a0 = acc[mi][ni][half * 2 + 0] + bv0;
                    float a1 = acc[mi][ni][half * 2 + 1] + bv1;
                    a0 = fmaxf(a0, 0.0f);
                    a1 = fmaxf(a1, 0.0f);
                    __nv_bfloat16 h0 = __float2bfloat16(a0);
                    __nv_bfloat16 h1 = __float2bfloat16(a1);
                    __nv_bfloat162 hip; hip.x = h0; hip.y = h1;
                    __nv_bfloat162 lop;
                    lop.x = __float2bfloat16(a0 - __bfloat162float(h0));
                    lop.y = __float2bfloat16(a1 - __bfloat162float(h1));
                    *(__nv_bfloat162*)&Hs[row * HSTR + col0]      = hip;
                    *(__nv_bfloat162*)&Hs[row * HSTR + 64 + col0] = lop;
                }
            }

        // stage Wf chunk: 64 rows x [hi64|lo64] -> Wfs stride HSTR
        for (int idx = tid; idx < 64 * 16; idx += 256) {
            int r = idx >> 4;
            int sub = idx & 15;
            int part = sub >> 3;            // 0=hi, 1=lo
            int q = sub & 7;
            uint4 v = *(const uint4*)&Wf16[(size_t)r * (2 * HH) + part * HH + nt * 64 + q * 8];
            *(uint4*)&Wfs[r * HSTR + part * 64 + q * 8] = v;
        }
        __syncthreads();

        // ---------------- phase B: p += Hs' (K=64, logical 192) x Wfs'^T ---
        for (int k0 = 0; k0 < 3 * 64; k0 += 16) {
            int seg = k0 >> 6;
            int kk = k0 & 63;
            int aoff = (seg == 2 ? 64 : 0) + kk;
            int boff = (seg == 1 ? 64 : 0) + kk;

            uint32_t afr[2][4];
            #pragma unroll
            for (int mi = 0; mi < 2; mi++) {
                int row = wm * 32 + mi * 16 + (lane & 15);
                ldmx4(afr[mi], &Hs[row * HSTR + aoff + (lane >> 4) * 8]);
            }
            uint32_t bfr[2][4];
            #pragma unroll
            for (int pr = 0; pr < 2; pr++) {
                int row = wn * 32 + pr * 16 + (lane & 15);
                ldmx4(bfr[pr], &Wfs[row * HSTR + boff + (lane >> 4) * 8]);
            }
            #pragma unroll
            for (int mi = 0; mi < 2; mi++)
                #pragma unroll
                for (int ni = 0; ni < 4; ni++) {
                    uint32_t bb[2];
                    bb[0] = bfr[ni >> 1][ni & 1];
                    bb[1] = bfr[ni >> 1][(ni & 1) + 2];
                    mma16816(acc2[mi][ni], afr[mi], bb);
                }
        }
        __syncthreads();   // protect Hs/Wfs before next nt overwrites
    }

    // epilogue: write p (stride PSTR, cols < CC, rows < M)
    #pragma unroll
    for (int mi = 0; mi < 2; mi++)
        #pragma unroll
        for (int ni = 0; ni < 4; ni++) {
            int col0 = wn * 32 + ni * 8 + 2 * (lane & 3);
            if (col0 >= CC) continue;
            int row0 = bm + wm * 32 + mi * 16 + (lane >> 2);
            if (row0 < M)
                *(float2*)&P[(size_t)row0 * PSTR + col0] =
                    make_float2(acc2[mi][ni][0], acc2[mi][ni][1]);
            if (row0 + 8 < M)
                *(float2*)&P[(size_t)(row0 + 8) * PSTR + col0] =
                    make_float2(acc2[mi][ni][2], acc2[mi][ni][3]);
        }
}

// ---------------- final aggregation at C=40: warp per node, float2 ----------
__global__ __launch_bounds__(256)
void aggregate_final_kernel(float* __restrict__ out) {
    int node = blockIdx.x * 8 + (threadIdx.x >> 5);
    int lane = threadIdx.x & 31;
    if (node >= NN) return;

    const float* __restrict__ p = g_p;
    int start = g_rowptr[node];
    int d = g_deg[node];
    float di = g_dinv[node];

    float ax = 0.0f, ay = 0.0f;
    #pragma unroll 4
    for (int j = 0; j < d; j++) {
        int2 e = g_epack[start + j];      // uniform across warp -> broadcast
        float w = __int_as_float(e.y);
        if (lane < CC / 2) {
            float2 v = *(const float2*)&p[(size_t)e.x * PSTR + 2 * lane];
            ax += w * v.x;
            ay += w * v.y;
        }
    }

    if (lane < CC / 2) {
        float2 self = *(const float2*)&p[(size_t)node * PSTR + 2 * lane];
        float dd = di * di;
        float v0 = di * ax + dd * self.x + g_biasf[2 * lane];
        float v1 = di * ay + dd * self.y + g_biasf[2 * lane + 1];
        *(float2*)&out[(size_t)node * CC + 2 * lane] = make_float2(v0, v1);
    }
}

// ---------------- launch ----------------------------------------------------
extern "C" void kernel_launch(void* const* d_in, const int* in_sizes, int n_in,
                              void* d_out, int out_size) {
    const float* x    = (const float*)d_in[0];
    const int*   ei   = (const int*)d_in[1];
    const float* W1   = (const float*)d_in[2];
    const float* b1   = (const float*)d_in[3];
    const float* W2   = (const float*)d_in[4];
    const float* b2   = (const float*)d_in[5];
    const float* Wout = (const float*)d_in[6];
    const float* bout = (const float*)d_in[7];
    float* out = (float*)d_out;

    const int* src = ei;         // edge_index[0]
    const int* dst = ei + EE;    // edge_index[1]

    __nv_bfloat16* a16;  cudaGetSymbolAddress((void**)&a16, g_a16);
    __nv_bfloat16* w16;  cudaGetSymbolAddress((void**)&w16, g_w16);
    __nv_bfloat16* wf16; cudaGetSymbolAddress((void**)&wf16, g_wf16);
    float* pbuf; cudaGetSymbolAddress((void**)&pbuf, g_p);

    cudaFuncSetAttribute(b2b_kernel, cudaFuncAttributeMaxDynamicSharedMemorySize,
                         41472 * (int)sizeof(__nv_bfloat16));

    // ---- prep: weights + zero deg (one kernel) ----
    prep_kernel<<<365, 256>>>(W1, W2, Wout, b2, bout);

    // ---- CSR build ----
    count_deg_kernel<<<(EE / 4 + 255) / 256, 256>>>(dst);
    scan_blocks_kernel<<<NB, 1024>>>();          // also computes dinv
    add_offsets_kernel<<<(NN + 255) / 256, 256>>>();   // inline partials prefix
    fill_csr_kernel<<<(EE / 4 + 255) / 256, 256>>>(src, dst);

    // ---- agg(x) -> split a16 (warp/node, float4, shuffle) ----
    aggregate_split_kernel<<<(NN + 7) / 8, 256>>>(x);

    // ---- fused B2B: p = relu(a16 @ W1'^T + b1) @ Wf'^T ----
    b2b_kernel<<<(NN + 127) / 128, 256, 41472 * sizeof(__nv_bfloat16)>>>(
        a16, w16, wf16, b1, pbuf, NN);

    // ---- final aggregation at C=40 -> out ----
    aggregate_final_kernel<<<(NN + 7) / 8, 256>>>(out);
}